// round 13
// baseline (speedup 1.0000x reference)
#include <cuda_runtime.h>
#include <cuda_bf16.h>
#include <math.h>
#include <stdint.h>

typedef __nv_bfloat16 bf16;

#define NB     2048
#define HB     1024            // half batch
#define BACKN  512
#define UNITSN 512
#define FOREN  128
#define THN    128
#define NLN    4
#define NCOEFN 8
#define KEXPN  (UNITSN * 9)   // 4608

#define WTOT   ((size_t)KEXPN * (4 * UNITSN + THN))

// ---------------------------------------------------------------------------
// Scratch (static device globals)
// ---------------------------------------------------------------------------
__device__ __align__(16) bf16  g_Ah[(size_t)NB * KEXPN];
__device__ __align__(16) bf16  g_Al[(size_t)NB * KEXPN];
__device__ __align__(16) bf16  g_Wh[WTOT];                     // per-layer slices
__device__ __align__(16) bf16  g_Wl[WTOT];
__device__ __align__(16) float g_H[2][(size_t)NB * UNITSN];    // FC split-K partials
__device__ __align__(16) float g_Pt[2][(size_t)NB * THN];      // theta split-K partials
__device__ __align__(16) bf16  g_Thh[(size_t)NB * THN];
__device__ __align__(16) bf16  g_Thl[(size_t)NB * THN];
__device__ __align__(16) bf16  g_Sch[(BACKN + FOREN) * THN];   // [t(640)][th]
__device__ __align__(16) bf16  g_Scl[(BACKN + FOREN) * THN];

// ---------------------------------------------------------------------------
// Streams + events (static-init: no mem delta during the run)
// s2 = weight prep (lowest priority), s3 = second batch-half pipeline.
// ---------------------------------------------------------------------------
struct SideStream {
    cudaStream_t s2, s3;
    cudaEvent_t evFork, evW[5], evB, evJoin, evG0;
    SideStream() {
        int lo = 0, hi = 0;
        cudaDeviceGetStreamPriorityRange(&lo, &hi);   // lo = least priority
        cudaStreamCreateWithPriority(&s2, cudaStreamNonBlocking, lo);
        cudaStreamCreateWithFlags(&s3, cudaStreamNonBlocking);
        cudaEventCreateWithFlags(&evFork, cudaEventDisableTiming);
        for (int i = 0; i < 5; i++)
            cudaEventCreateWithFlags(&evW[i], cudaEventDisableTiming);
        cudaEventCreateWithFlags(&evB, cudaEventDisableTiming);
        cudaEventCreateWithFlags(&evJoin, cudaEventDisableTiming);
        cudaEventCreateWithFlags(&evG0, cudaEventDisableTiming);
    }
};
static SideStream g_ss;

// ---------------------------------------------------------------------------
// PTX helpers (arch-generic, sm_80-level)
// ---------------------------------------------------------------------------
__device__ __forceinline__ uint32_t smem_u32(const void* p) {
    uint32_t a;
    asm("{ .reg .u64 t; cvta.to.shared.u64 t, %1; cvt.u32.u64 %0, t; }"
        : "=r"(a) : "l"(p));
    return a;
}
__device__ __forceinline__ void cp16(uint32_t dst, const void* src) {
    asm volatile("cp.async.cg.shared.global [%0], [%1], 16;" :: "r"(dst), "l"(src));
}
__device__ __forceinline__ void cp_commit() {
    asm volatile("cp.async.commit_group;" ::: "memory");
}
template <int N_>
__device__ __forceinline__ void cp_wait() {
    asm volatile("cp.async.wait_group %0;" :: "n"(N_) : "memory");
}
__device__ __forceinline__ void ldsm_x4(uint32_t* r, uint32_t addr) {
    asm volatile("ldmatrix.sync.aligned.m8n8.x4.shared.b16 {%0,%1,%2,%3}, [%4];"
        : "=r"(r[0]), "=r"(r[1]), "=r"(r[2]), "=r"(r[3]) : "r"(addr));
}
__device__ __forceinline__ void mma16816(float* c, const uint32_t* a, const uint32_t* b) {
    asm volatile(
        "mma.sync.aligned.m16n8k16.row.col.f32.bf16.bf16.f32 "
        "{%0,%1,%2,%3}, {%4,%5,%6,%7}, {%8,%9}, {%0,%1,%2,%3};"
        : "+f"(c[0]), "+f"(c[1]), "+f"(c[2]), "+f"(c[3])
        : "r"(a[0]), "r"(a[1]), "r"(a[2]), "r"(a[3]), "r"(b[0]), "r"(b[1]));
}

// smem addressing: 128B rows (BK=64 bf16), 8x16B chunks, SW128-style XOR
__device__ __forceinline__ uint32_t swz(int row, int c) {
    return (uint32_t)(row * 128 + ((c ^ (row & 7)) << 4));
}

__device__ __forceinline__ void split2(float x, bf16& h, bf16& l) {
    h = __float2bfloat16(x);
    l = __float2bfloat16(x - __bfloat162float(h));
}

// ---------------------------------------------------------------------------
// mma.sync GEMM: C = (Ah+Al)[M,Kstride] @ (Bh+Bl)^T  (B stored [N][Kstride])
// Per-CTA K-range [z*K, z*K+K).
// EPI 0: split-K partial -> C + z*ZOFF (ZOFF passed in N2), row stride NS1.
// EPI 2: two-region float remap (z grid = 1).
// BK=64, 2-stage cp.async, 2 CTAs/SM, 3-term bf16 split, fp32 accum.
// ---------------------------------------------------------------------------
template <int BM, int BN, int WM, int WN, int EPI>
__global__ __launch_bounds__(256, 2) void gemm_mma(
    const bf16* __restrict__ Ah, const bf16* __restrict__ Al,
    const bf16* __restrict__ Bh, const bf16* __restrict__ Bl,
    float* __restrict__ C, float* __restrict__ C2,
    int M, int N, int K, int Kstride, int NS1, int N2, int nsplit)
{
    constexpr int BK     = 64;
    constexpr int ROWB   = BK * 2;
    constexpr int ABYTES = BM * ROWB;
    constexpr int BBYTES = BN * ROWB;
    constexpr int STAGE  = 2 * ABYTES + 2 * BBYTES;
    constexpr int MT = WM / 16;
    constexpr int NP = WN / 16;
    static_assert((BM / WM) * (BN / WN) == 8, "8 warps");

    extern __shared__ __align__(16) char smem[];

    const int tid  = threadIdx.x;
    const int wid  = tid >> 5;
    const int lane = tid & 31;
    constexpr int WNN = BN / WN;
    const int wm = wid / WNN, wn = wid % WNN;
    const int bm = blockIdx.y * BM, bn = blockIdx.x * BN;
    const int kbase = blockIdx.z * K;
    const uint32_t sbase = smem_u32(smem);
    const int KCH = K >> 6;

    auto load_stage = [&](int s, int c) {
        uint32_t st = sbase + s * STAGE;
        int k0 = kbase + c * BK;
#pragma unroll 2
        for (int idx = tid; idx < BM * 8; idx += 256) {
            int r = idx >> 3, ch = idx & 7;
            size_t g = (size_t)(bm + r) * Kstride + k0 + ch * 8;
            cp16(st + swz(r, ch), Ah + g);
            cp16(st + ABYTES + swz(r, ch), Al + g);
        }
#pragma unroll 2
        for (int idx = tid; idx < BN * 8; idx += 256) {
            int r = idx >> 3, ch = idx & 7;
            size_t g = (size_t)(bn + r) * Kstride + k0 + ch * 8;
            cp16(st + 2 * ABYTES + swz(r, ch), Bh + g);
            cp16(st + 2 * ABYTES + BBYTES + swz(r, ch), Bl + g);
        }
        cp_commit();
    };

    float acc[MT][NP * 2][4];
#pragma unroll
    for (int i = 0; i < MT; i++)
#pragma unroll
        for (int j = 0; j < NP * 2; j++)
#pragma unroll
            for (int q = 0; q < 4; q++) acc[i][j][q] = 0.0f;

    uint32_t ah[2][MT][4], al[2][MT][4], bh[2][NP][4], bl[2][NP][4];

    const int a_row0 = wm * WM + (lane & 15);
    const int a_sel  = lane >> 4;
    const int b_row0 = wn * WN + (lane & 7) + ((lane & 16) >> 1);
    const int b_sel  = (lane >> 3) & 1;

    auto ld_frags = [&](int buf, uint32_t st, int ks) {
#pragma unroll
        for (int mt = 0; mt < MT; ++mt) {
            int row = a_row0 + mt * 16;
            int ch  = ks * 2 + a_sel;
            ldsm_x4(ah[buf][mt], st + swz(row, ch));
            ldsm_x4(al[buf][mt], st + ABYTES + swz(row, ch));
        }
#pragma unroll
        for (int p = 0; p < NP; ++p) {
            int row = b_row0 + p * 16;
            int ch  = ks * 2 + b_sel;
            ldsm_x4(bh[buf][p], st + 2 * ABYTES + swz(row, ch));
            ldsm_x4(bl[buf][p], st + 2 * ABYTES + BBYTES + swz(row, ch));
        }
    };
    auto do_mma = [&](int buf) {
#pragma unroll
        for (int t = 0; t < 3; ++t)
#pragma unroll
            for (int mt = 0; mt < MT; ++mt)
#pragma unroll
                for (int p = 0; p < NP; ++p) {
                    const uint32_t* af = (t == 2) ? al[buf][mt] : ah[buf][mt];
                    const uint32_t* bf = (t == 1) ? bl[buf][p]  : bh[buf][p];
                    mma16816(acc[mt][2 * p],     af, bf);
                    mma16816(acc[mt][2 * p + 1], af, bf + 2);
                }
    };

    load_stage(0, 0);

    for (int c = 0; c < KCH; ++c) {
        cp_wait<0>();
        __syncthreads();
        uint32_t st = sbase + (c & 1) * STAGE;
        ld_frags(0, st, 0);
        if (c + 1 < KCH) load_stage((c + 1) & 1, c + 1);
        else cp_commit();
#pragma unroll
        for (int ks = 0; ks < 4; ++ks) {
            if (ks < 3) ld_frags((ks + 1) & 1, st, ks + 1);
            do_mma(ks & 1);
        }
    }

    // ---- epilogue ----
    float* Cw;
    int Nw = NS1;
    int bnw = bn;
    if (EPI == 0) {
        Cw = C + (size_t)blockIdx.z * (size_t)N2;   // N2 = z-stride (elements)
    } else {
        Cw = C;
        if (bn >= nsplit) { Cw = C2; Nw = N2; bnw = bn - nsplit; }
    }
#pragma unroll
    for (int mt = 0; mt < MT; ++mt) {
        int m0 = bm + wm * WM + mt * 16 + (lane >> 2);
#pragma unroll
        for (int nt = 0; nt < NP * 2; ++nt) {
            int n0 = bnw + wn * WN + nt * 8 + (lane & 3) * 2;
            *(float2*)(Cw + (size_t)m0 * Nw + n0)       = make_float2(acc[mt][nt][0], acc[mt][nt][1]);
            *(float2*)(Cw + (size_t)(m0 + 8) * Nw + n0) = make_float2(acc[mt][nt][2], acc[mt][nt][3]);
        }
    }
}

// ---------------------------------------------------------------------------
// Expansion (closed-form uniform cubic B-spline) + bf16 split.
// Input h = h0 (+ h1 if non-null): fuses the split-K reduction.
// ---------------------------------------------------------------------------
__global__ __launch_bounds__(256) void expand_kernel(
    const float* __restrict__ h0, const float* __restrict__ h1,
    bf16* __restrict__ Ah, bf16* __restrict__ Al) {
    __shared__ __align__(16) bf16 s_hi[256 * 9];
    __shared__ __align__(16) bf16 s_lo[256 * 9];

    int tid  = threadIdx.x;
    int gid  = blockIdx.x;
    int b    = gid >> 1;
    int half = gid & 1;
    int u    = half * 256 + tid;

    size_t hidx = (size_t)b * UNITSN + u;
    float x = h0[hidx];
    if (h1) x += h1[hidx];

    float vals[9];
    vals[0] = x / (1.0f + expf(-x));
#pragma unroll
    for (int k = 1; k < 9; k++) vals[k] = 0.0f;

    int c = -1;
#pragma unroll
    for (int j = 0; j < 12; j++) {
        float gj = (float)(0.4 * (double)(j - 3) - 1.0);
        c += (x >= gj) ? 1 : 0;
    }
    if (c >= 0 && c <= 10) {
        float gc = (float)c * 0.4f - 2.2f;
        float t  = (x - gc) * 2.5f;
        float t2 = t * t, t3 = t2 * t;
        float omt = 1.0f - t;
        float w0 = t3 * (1.0f / 6.0f);
        float w1 = (1.0f + 3.0f * t + 3.0f * t2 - 3.0f * t3) * (1.0f / 6.0f);
        float w2 = (4.0f - 6.0f * t2 + 3.0f * t3) * (1.0f / 6.0f);
        float w3 = omt * omt * omt * (1.0f / 6.0f);
        if (c <= 7)                    vals[1 + c]   = w0;
        if (c - 1 >= 0 && c - 1 <= 7)  vals[c]       = w1;
        if (c - 2 >= 0 && c - 2 <= 7)  vals[c - 1]   = w2;
        if (c - 3 >= 0)                vals[c - 2]   = w3;
    }

#pragma unroll
    for (int f = 0; f < 9; f++) {
        bf16 hv, lv;
        split2(vals[f], hv, lv);
        s_hi[tid * 9 + f] = hv;
        s_lo[tid * 9 + f] = lv;
    }
    __syncthreads();

    size_t elem_base = (size_t)b * KEXPN + half * 2304;
    const uint4* sh = (const uint4*)s_hi;
    const uint4* sl = (const uint4*)s_lo;
    uint4* dh = (uint4*)(Ah + elem_base);
    uint4* dl = (uint4*)(Al + elem_base);
#pragma unroll 2
    for (int j = tid; j < 288; j += 256) { dh[j] = sh[j]; dl[j] = sl[j]; }
}

// ---------------------------------------------------------------------------
// Combine split-K partials -> bf16 hi/lo (theta)
// ---------------------------------------------------------------------------
__global__ void combine_split_kernel(const float* __restrict__ p0,
                                     const float* __restrict__ p1,
                                     bf16* __restrict__ hi, bf16* __restrict__ lo,
                                     int n) {
    int i = blockIdx.x * blockDim.x + threadIdx.x;
    if (i < n) {
        float v = p0[i] + p1[i];
        bf16 h, l;
        split2(v, h, l);
        hi[i] = h; lo[i] = l;
    }
}

// ---------------------------------------------------------------------------
// Weight pack + split into [N][K] bf16 hi/lo, smem transpose tile (32x32)
// ---------------------------------------------------------------------------
__global__ __launch_bounds__(256) void prepw_kernel(
    const float* __restrict__ coef, const float* __restrict__ sb,
    const float* __restrict__ ssp,
    bf16* __restrict__ Wh, bf16* __restrict__ Wl, int N) {
    extern __shared__ __align__(16) char psm[];
    bf16* s_hi = (bf16*)psm;              // [32][288]
    bf16* s_lo = s_hi + 32 * 288;

    int tid = threadIdx.x;
    int ob0 = blockIdx.x * 32;
    int ib0 = blockIdx.y * 32;

    for (int t = tid; t < 32 * 32; t += 256) {
        int i_l = t >> 5, o_l = t & 31;
        int i = ib0 + i_l, o = ob0 + o_l;
        size_t idx = (size_t)i * N + o;
        float s   = ssp[idx];
        float sbv = sb[idx];
        const float4* cp = (const float4*)(coef + idx * NCOEFN);
        float4 c0 = cp[0], c1 = cp[1];
        float cv[8] = {c0.x, c0.y, c0.z, c0.w, c1.x, c1.y, c1.z, c1.w};
        bf16* rh = s_hi + o_l * 288 + i_l * 9;
        bf16* rl = s_lo + o_l * 288 + i_l * 9;
        bf16 hv, lv;
        split2(sbv, hv, lv); rh[0] = hv; rl[0] = lv;
#pragma unroll
        for (int k = 0; k < 8; k++) {
            split2(cv[k] * s, hv, lv);
            rh[1 + k] = hv; rl[1 + k] = lv;
        }
    }
    __syncthreads();

    for (int j = tid; j < 32 * 36; j += 256) {
        int o_l = j / 36, q = j - o_l * 36;
        size_t ebase = (size_t)(ob0 + o_l) * KEXPN + (size_t)ib0 * 9;
        ((uint4*)(Wh + ebase))[q] = ((const uint4*)(s_hi + o_l * 288))[q];
        ((uint4*)(Wl + ebase))[q] = ((const uint4*)(s_lo + o_l * 288))[q];
    }
}

// ---------------------------------------------------------------------------
// Seasonal basis (double trig), combined [640][128] layout, bf16 split
// ---------------------------------------------------------------------------
__global__ void basis_kernel(bf16* Sbh, bf16* Sbl, bf16* Sfh, bf16* Sfl) {
    int idx = blockIdx.x * blockDim.x + threadIdx.x;
    const double step = (639.0 / 640.0) / 639.0;
    const double TWO_PI = 6.283185307179586476925286766559;
    int total_b = BACKN * THN;
    int total_f = FOREN * THN;
    if (idx < total_b) {
        int t = idx / THN, r = idx % THN;
        double lin = (double)t * step;
        int rr = (r < 64) ? r : r - 64;
        double f = (rr == 63) ? 640.0 : (double)rr * (640.0 / 63.0);
        double a = TWO_PI * f * lin;
        bf16 hv, lv;
        split2((float)((r < 64) ? cos(a) : sin(a)), hv, lv);
        Sbh[idx] = hv; Sbl[idx] = lv;
    } else if (idx < total_b + total_f) {
        int j = idx - total_b;
        int t = j / THN, r = j % THN;
        int tt = t + BACKN;
        double lin = (tt == 639) ? (639.0 / 640.0) : (double)tt * step;
        int rr = (r < 64) ? r : r - 64;
        double f = (rr == 63) ? 640.0 : (double)rr * (640.0 / 63.0);
        double a = TWO_PI * f * lin;
        bf16 hv, lv;
        split2((float)((r < 64) ? cos(a) : sin(a)), hv, lv);
        Sfh[j] = hv; Sfl[j] = lv;
    }
}

// ---------------------------------------------------------------------------
// Launch: two half-batch pipelines, SKEWED one stage apart so the expand
// phases of one half overlap the GEMM phases of the other.
// prepw + basis on low-priority side stream s2.
// ---------------------------------------------------------------------------
extern "C" void kernel_launch(void* const* d_in, const int* in_sizes, int n_in,
                              void* d_out, int out_size) {
    (void)in_sizes; (void)n_in; (void)out_size;
    const float* x       = (const float*)d_in[0];
    const float* coef_fc = (const float*)d_in[1];
    const float* sb_fc   = (const float*)d_in[2];
    const float* ssp_fc  = (const float*)d_in[3];
    const float* coef_th = (const float*)d_in[4];
    const float* sb_th   = (const float*)d_in[5];
    const float* ssp_th  = (const float*)d_in[6];
    float* out = (float*)d_out;

    bf16 *Ah, *Al, *Wh, *Wl, *Thh, *Thl, *Sch, *Scl;
    float *Hbase, *Ptbase;
    cudaGetSymbolAddress((void**)&Ah, g_Ah);
    cudaGetSymbolAddress((void**)&Al, g_Al);
    cudaGetSymbolAddress((void**)&Wh, g_Wh);
    cudaGetSymbolAddress((void**)&Wl, g_Wl);
    cudaGetSymbolAddress((void**)&Hbase, g_H);
    cudaGetSymbolAddress((void**)&Ptbase, g_Pt);
    cudaGetSymbolAddress((void**)&Thh, g_Thh);
    cudaGetSymbolAddress((void**)&Thl, g_Thl);
    cudaGetSymbolAddress((void**)&Sch, g_Sch);
    cudaGetSymbolAddress((void**)&Scl, g_Scl);

    const size_t WSLICE  = (size_t)KEXPN * UNITSN;
    const size_t WOFF_TH = 4 * WSLICE;
    const size_t PZS_FC  = (size_t)NB * UNITSN;    // z-stride for FC partials
    const size_t PZS_TH  = (size_t)NB * THN;       // z-stride for theta partials

    const int SMEM_FC = 2 * (2 * 128 * 128 + 2 * 64 * 128);   // 96 KB
    const int SMEM_TH = 2 * (2 * 64 * 128 + 2 * 32 * 128);    // 48 KB
    const int SMEM_PW = 2 * 32 * 288 * 2;                     // 36 KB
    cudaFuncSetAttribute((const void*)gemm_mma<128, 64, 32, 32, 0>,
                         cudaFuncAttributeMaxDynamicSharedMemorySize, SMEM_FC);
    cudaFuncSetAttribute((const void*)gemm_mma<128, 64, 32, 32, 2>,
                         cudaFuncAttributeMaxDynamicSharedMemorySize, SMEM_FC);
    cudaFuncSetAttribute((const void*)gemm_mma<64, 32, 16, 16, 0>,
                         cudaFuncAttributeMaxDynamicSharedMemorySize, SMEM_TH);
    cudaFuncSetAttribute((const void*)prepw_kernel,
                         cudaFuncAttributeMaxDynamicSharedMemorySize, SMEM_PW);

    cudaStream_t s2 = g_ss.s2;
    cudaStream_t s3 = g_ss.s3;

    // ---- fork side streams ----
    cudaEventRecord(g_ss.evFork, 0);
    cudaStreamWaitEvent(s2, g_ss.evFork, 0);
    cudaStreamWaitEvent(s3, g_ss.evFork, 0);

    // s2: weight packs + basis
    for (int l = 0; l < NLN; l++) {
        prepw_kernel<<<dim3(UNITSN / 32, UNITSN / 32), 256, SMEM_PW, s2>>>(
            coef_fc + (size_t)l * UNITSN * UNITSN * NCOEFN,
            sb_fc  + (size_t)l * UNITSN * UNITSN,
            ssp_fc + (size_t)l * UNITSN * UNITSN,
            Wh + l * WSLICE, Wl + l * WSLICE, UNITSN);
        cudaEventRecord(g_ss.evW[l], s2);
    }
    prepw_kernel<<<dim3(THN / 32, UNITSN / 32), 256, SMEM_PW, s2>>>(
        coef_th, sb_th, ssp_th, Wh + WOFF_TH, Wl + WOFF_TH, THN);
    cudaEventRecord(g_ss.evW[4], s2);
    {
        int total = BACKN * THN + FOREN * THN;
        basis_kernel<<<(total + 255) / 256, 256, 0, s2>>>(
            Sch, Scl, Sch + (size_t)BACKN * THN, Scl + (size_t)BACKN * THN);
        cudaEventRecord(g_ss.evB, s2);
    }

    // ---- two half-batch pipelines, skewed by one stage ----
    for (int h = 0; h < 2; ++h) {
        cudaStream_t st = (h == 0) ? (cudaStream_t)0 : s3;
        const float* xh  = x + (size_t)h * HB * UNITSN;
        bf16* Ahh = Ah + (size_t)h * HB * KEXPN;
        bf16* Alh = Al + (size_t)h * HB * KEXPN;
        float* P0h  = Hbase  + (size_t)h * HB * UNITSN;   // FC partial z=0
        float* P1h  = P0h + PZS_FC;                       // FC partial z=1
        float* Pt0h = Ptbase + (size_t)h * HB * THN;      // theta partial z=0
        float* Pt1h = Pt0h + PZS_TH;                      // theta partial z=1
        bf16* Thhh = Thh + (size_t)h * HB * THN;
        bf16* Thlh = Thl + (size_t)h * HB * THN;

        // skew: half-1 starts only after half-0's first FC GEMM completes
        if (h == 1) cudaStreamWaitEvent(st, g_ss.evG0, 0);

        // FC chain
        const float* hin0 = xh;
        const float* hin1 = nullptr;
        for (int l = 0; l < NLN; l++) {
            expand_kernel<<<HB * 2, 256, 0, st>>>(hin0, hin1, Ahh, Alh);
            cudaStreamWaitEvent(st, g_ss.evW[l], 0);
            gemm_mma<128, 64, 32, 32, 0>
                <<<dim3(UNITSN / 64, HB / 128, 2), 256, SMEM_FC, st>>>(
                Ahh, Alh, Wh + l * WSLICE, Wl + l * WSLICE, P0h, nullptr,
                HB, UNITSN, KEXPN / 2, KEXPN, UNITSN, (int)PZS_FC, UNITSN);
            if (h == 0 && l == 0) cudaEventRecord(g_ss.evG0, st);
            hin0 = P0h; hin1 = P1h;
        }

        // theta layer (512 -> 128), split-K=2 into dedicated g_Pt
        expand_kernel<<<HB * 2, 256, 0, st>>>(hin0, hin1, Ahh, Alh);
        cudaStreamWaitEvent(st, g_ss.evW[4], 0);
        gemm_mma<64, 32, 16, 16, 0>
            <<<dim3(THN / 32, HB / 64, 2), 256, SMEM_TH, st>>>(
            Ahh, Alh, Wh + WOFF_TH, Wl + WOFF_TH, Pt0h, nullptr,
            HB, THN, KEXPN / 2, KEXPN, THN, (int)PZS_TH, THN);
        combine_split_kernel<<<(HB * THN + 255) / 256, 256, 0, st>>>(
            Pt0h, Pt1h, Thhh, Thlh, HB * THN);

        // backcast + forecast merged: theta @ [Sb|Sf] (N=640, K=128)
        cudaStreamWaitEvent(st, g_ss.evB, 0);
        gemm_mma<128, 64, 32, 32, 2>
            <<<dim3((BACKN + FOREN) / 64, HB / 128, 1), 256, SMEM_FC, st>>>(
            Thhh, Thlh, Sch, Scl,
            out + (size_t)h * HB * BACKN,
            out + (size_t)NB * BACKN + (size_t)h * HB * FOREN,
            HB, BACKN + FOREN, THN, THN, BACKN, FOREN, BACKN);
    }

    // ---- join s3 back into the capture origin stream ----
    cudaEventRecord(g_ss.evJoin, s3);
    cudaStreamWaitEvent((cudaStream_t)0, g_ss.evJoin, 0);
}

// round 14
// speedup vs baseline: 1.0340x; 1.0340x over previous
#include <cuda_runtime.h>
#include <cuda_bf16.h>
#include <math.h>
#include <stdint.h>

typedef __nv_bfloat16 bf16;

#define NB     2048
#define HB     1024            // half batch
#define BACKN  512
#define UNITSN 512
#define FOREN  128
#define THN    128
#define NLN    4
#define NCOEFN 8
#define KEXPN  (UNITSN * 9)   // 4608

#define WTOT   ((size_t)KEXPN * (4 * UNITSN + THN))

// ---------------------------------------------------------------------------
// Scratch (static device globals)
// ---------------------------------------------------------------------------
__device__ __align__(16) bf16  g_Ah[(size_t)NB * KEXPN];
__device__ __align__(16) bf16  g_Al[(size_t)NB * KEXPN];
__device__ __align__(16) bf16  g_Wh[WTOT];                     // per-layer slices
__device__ __align__(16) bf16  g_Wl[WTOT];
__device__ __align__(16) float g_H[2][(size_t)NB * UNITSN];    // FC split-K partials
__device__ __align__(16) float g_Pt[2][(size_t)NB * THN];      // theta split-K partials
__device__ __align__(16) bf16  g_Thh[(size_t)NB * THN];
__device__ __align__(16) bf16  g_Thl[(size_t)NB * THN];
__device__ __align__(16) bf16  g_Sch[(BACKN + FOREN) * THN];   // [t(640)][th]
__device__ __align__(16) bf16  g_Scl[(BACKN + FOREN) * THN];

// ---------------------------------------------------------------------------
// Streams + events (static-init: no mem delta during the run)
// s2 = weight prep (lowest priority), s3 = second batch-half pipeline.
// ---------------------------------------------------------------------------
struct SideStream {
    cudaStream_t s2, s3;
    cudaEvent_t evFork, evW[5], evB, evJoin, evE0;
    SideStream() {
        int lo = 0, hi = 0;
        cudaDeviceGetStreamPriorityRange(&lo, &hi);   // lo = least priority
        cudaStreamCreateWithPriority(&s2, cudaStreamNonBlocking, lo);
        cudaStreamCreateWithFlags(&s3, cudaStreamNonBlocking);
        cudaEventCreateWithFlags(&evFork, cudaEventDisableTiming);
        for (int i = 0; i < 5; i++)
            cudaEventCreateWithFlags(&evW[i], cudaEventDisableTiming);
        cudaEventCreateWithFlags(&evB, cudaEventDisableTiming);
        cudaEventCreateWithFlags(&evJoin, cudaEventDisableTiming);
        cudaEventCreateWithFlags(&evE0, cudaEventDisableTiming);
    }
};
static SideStream g_ss;

// ---------------------------------------------------------------------------
// PTX helpers (arch-generic, sm_80-level)
// ---------------------------------------------------------------------------
__device__ __forceinline__ uint32_t smem_u32(const void* p) {
    uint32_t a;
    asm("{ .reg .u64 t; cvta.to.shared.u64 t, %1; cvt.u32.u64 %0, t; }"
        : "=r"(a) : "l"(p));
    return a;
}
__device__ __forceinline__ void cp16(uint32_t dst, const void* src) {
    asm volatile("cp.async.cg.shared.global [%0], [%1], 16;" :: "r"(dst), "l"(src));
}
__device__ __forceinline__ void cp_commit() {
    asm volatile("cp.async.commit_group;" ::: "memory");
}
template <int N_>
__device__ __forceinline__ void cp_wait() {
    asm volatile("cp.async.wait_group %0;" :: "n"(N_) : "memory");
}
__device__ __forceinline__ void ldsm_x4(uint32_t* r, uint32_t addr) {
    asm volatile("ldmatrix.sync.aligned.m8n8.x4.shared.b16 {%0,%1,%2,%3}, [%4];"
        : "=r"(r[0]), "=r"(r[1]), "=r"(r[2]), "=r"(r[3]) : "r"(addr));
}
__device__ __forceinline__ void mma16816(float* c, const uint32_t* a, const uint32_t* b) {
    asm volatile(
        "mma.sync.aligned.m16n8k16.row.col.f32.bf16.bf16.f32 "
        "{%0,%1,%2,%3}, {%4,%5,%6,%7}, {%8,%9}, {%0,%1,%2,%3};"
        : "+f"(c[0]), "+f"(c[1]), "+f"(c[2]), "+f"(c[3])
        : "r"(a[0]), "r"(a[1]), "r"(a[2]), "r"(a[3]), "r"(b[0]), "r"(b[1]));
}

// smem addressing: 128B rows (BK=64 bf16), 8x16B chunks, SW128-style XOR
__device__ __forceinline__ uint32_t swz(int row, int c) {
    return (uint32_t)(row * 128 + ((c ^ (row & 7)) << 4));
}

__device__ __forceinline__ void split2(float x, bf16& h, bf16& l) {
    h = __float2bfloat16(x);
    l = __float2bfloat16(x - __bfloat162float(h));
}

// ---------------------------------------------------------------------------
// mma.sync GEMM: C = (Ah+Al)[M,Kstride] @ (Bh+Bl)^T  (B stored [N][Kstride])
// Per-CTA K-range [z*K, z*K+K).
// EPI 0: split-K partial -> C + z*ZOFF (ZOFF passed in N2), row stride NS1.
// EPI 2: two-region float remap (z grid = 1).
// BK=64, 2-stage cp.async, 2 CTAs/SM, 3-term bf16 split, fp32 accum.
// ---------------------------------------------------------------------------
template <int BM, int BN, int WM, int WN, int EPI>
__global__ __launch_bounds__(256, 2) void gemm_mma(
    const bf16* __restrict__ Ah, const bf16* __restrict__ Al,
    const bf16* __restrict__ Bh, const bf16* __restrict__ Bl,
    float* __restrict__ C, float* __restrict__ C2,
    int M, int N, int K, int Kstride, int NS1, int N2, int nsplit)
{
    constexpr int BK     = 64;
    constexpr int ROWB   = BK * 2;
    constexpr int ABYTES = BM * ROWB;
    constexpr int BBYTES = BN * ROWB;
    constexpr int STAGE  = 2 * ABYTES + 2 * BBYTES;
    constexpr int MT = WM / 16;
    constexpr int NP = WN / 16;
    static_assert((BM / WM) * (BN / WN) == 8, "8 warps");

    extern __shared__ __align__(16) char smem[];

    const int tid  = threadIdx.x;
    const int wid  = tid >> 5;
    const int lane = tid & 31;
    constexpr int WNN = BN / WN;
    const int wm = wid / WNN, wn = wid % WNN;
    const int bm = blockIdx.y * BM, bn = blockIdx.x * BN;
    const int kbase = blockIdx.z * K;
    const uint32_t sbase = smem_u32(smem);
    const int KCH = K >> 6;

    auto load_stage = [&](int s, int c) {
        uint32_t st = sbase + s * STAGE;
        int k0 = kbase + c * BK;
#pragma unroll 2
        for (int idx = tid; idx < BM * 8; idx += 256) {
            int r = idx >> 3, ch = idx & 7;
            size_t g = (size_t)(bm + r) * Kstride + k0 + ch * 8;
            cp16(st + swz(r, ch), Ah + g);
            cp16(st + ABYTES + swz(r, ch), Al + g);
        }
#pragma unroll 2
        for (int idx = tid; idx < BN * 8; idx += 256) {
            int r = idx >> 3, ch = idx & 7;
            size_t g = (size_t)(bn + r) * Kstride + k0 + ch * 8;
            cp16(st + 2 * ABYTES + swz(r, ch), Bh + g);
            cp16(st + 2 * ABYTES + BBYTES + swz(r, ch), Bl + g);
        }
        cp_commit();
    };

    float acc[MT][NP * 2][4];
#pragma unroll
    for (int i = 0; i < MT; i++)
#pragma unroll
        for (int j = 0; j < NP * 2; j++)
#pragma unroll
            for (int q = 0; q < 4; q++) acc[i][j][q] = 0.0f;

    uint32_t ah[2][MT][4], al[2][MT][4], bh[2][NP][4], bl[2][NP][4];

    const int a_row0 = wm * WM + (lane & 15);
    const int a_sel  = lane >> 4;
    const int b_row0 = wn * WN + (lane & 7) + ((lane & 16) >> 1);
    const int b_sel  = (lane >> 3) & 1;

    auto ld_frags = [&](int buf, uint32_t st, int ks) {
#pragma unroll
        for (int mt = 0; mt < MT; ++mt) {
            int row = a_row0 + mt * 16;
            int ch  = ks * 2 + a_sel;
            ldsm_x4(ah[buf][mt], st + swz(row, ch));
            ldsm_x4(al[buf][mt], st + ABYTES + swz(row, ch));
        }
#pragma unroll
        for (int p = 0; p < NP; ++p) {
            int row = b_row0 + p * 16;
            int ch  = ks * 2 + b_sel;
            ldsm_x4(bh[buf][p], st + 2 * ABYTES + swz(row, ch));
            ldsm_x4(bl[buf][p], st + 2 * ABYTES + BBYTES + swz(row, ch));
        }
    };
    auto do_mma = [&](int buf) {
#pragma unroll
        for (int t = 0; t < 3; ++t)
#pragma unroll
            for (int mt = 0; mt < MT; ++mt)
#pragma unroll
                for (int p = 0; p < NP; ++p) {
                    const uint32_t* af = (t == 2) ? al[buf][mt] : ah[buf][mt];
                    const uint32_t* bf = (t == 1) ? bl[buf][p]  : bh[buf][p];
                    mma16816(acc[mt][2 * p],     af, bf);
                    mma16816(acc[mt][2 * p + 1], af, bf + 2);
                }
    };

    load_stage(0, 0);

    for (int c = 0; c < KCH; ++c) {
        cp_wait<0>();
        __syncthreads();
        uint32_t st = sbase + (c & 1) * STAGE;
        ld_frags(0, st, 0);
        if (c + 1 < KCH) load_stage((c + 1) & 1, c + 1);
        else cp_commit();
#pragma unroll
        for (int ks = 0; ks < 4; ++ks) {
            if (ks < 3) ld_frags((ks + 1) & 1, st, ks + 1);
            do_mma(ks & 1);
        }
    }

    // ---- epilogue ----
    float* Cw;
    int Nw = NS1;
    int bnw = bn;
    if (EPI == 0) {
        Cw = C + (size_t)blockIdx.z * (size_t)N2;   // N2 = z-stride (elements)
    } else {
        Cw = C;
        if (bn >= nsplit) { Cw = C2; Nw = N2; bnw = bn - nsplit; }
    }
#pragma unroll
    for (int mt = 0; mt < MT; ++mt) {
        int m0 = bm + wm * WM + mt * 16 + (lane >> 2);
#pragma unroll
        for (int nt = 0; nt < NP * 2; ++nt) {
            int n0 = bnw + wn * WN + nt * 8 + (lane & 3) * 2;
            *(float2*)(Cw + (size_t)m0 * Nw + n0)       = make_float2(acc[mt][nt][0], acc[mt][nt][1]);
            *(float2*)(Cw + (size_t)(m0 + 8) * Nw + n0) = make_float2(acc[mt][nt][2], acc[mt][nt][3]);
        }
    }
}

// ---------------------------------------------------------------------------
// Expansion (closed-form uniform cubic B-spline) + bf16 split.
// Input h = h0 (+ h1 if non-null): fuses the split-K reduction.
// ---------------------------------------------------------------------------
__global__ __launch_bounds__(256) void expand_kernel(
    const float* __restrict__ h0, const float* __restrict__ h1,
    bf16* __restrict__ Ah, bf16* __restrict__ Al) {
    __shared__ __align__(16) bf16 s_hi[256 * 9];
    __shared__ __align__(16) bf16 s_lo[256 * 9];

    int tid  = threadIdx.x;
    int gid  = blockIdx.x;
    int b    = gid >> 1;
    int half = gid & 1;
    int u    = half * 256 + tid;

    size_t hidx = (size_t)b * UNITSN + u;
    float x = h0[hidx];
    if (h1) x += h1[hidx];

    float vals[9];
    vals[0] = x / (1.0f + expf(-x));
#pragma unroll
    for (int k = 1; k < 9; k++) vals[k] = 0.0f;

    int c = -1;
#pragma unroll
    for (int j = 0; j < 12; j++) {
        float gj = (float)(0.4 * (double)(j - 3) - 1.0);
        c += (x >= gj) ? 1 : 0;
    }
    if (c >= 0 && c <= 10) {
        float gc = (float)c * 0.4f - 2.2f;
        float t  = (x - gc) * 2.5f;
        float t2 = t * t, t3 = t2 * t;
        float omt = 1.0f - t;
        float w0 = t3 * (1.0f / 6.0f);
        float w1 = (1.0f + 3.0f * t + 3.0f * t2 - 3.0f * t3) * (1.0f / 6.0f);
        float w2 = (4.0f - 6.0f * t2 + 3.0f * t3) * (1.0f / 6.0f);
        float w3 = omt * omt * omt * (1.0f / 6.0f);
        if (c <= 7)                    vals[1 + c]   = w0;
        if (c - 1 >= 0 && c - 1 <= 7)  vals[c]       = w1;
        if (c - 2 >= 0 && c - 2 <= 7)  vals[c - 1]   = w2;
        if (c - 3 >= 0)                vals[c - 2]   = w3;
    }

#pragma unroll
    for (int f = 0; f < 9; f++) {
        bf16 hv, lv;
        split2(vals[f], hv, lv);
        s_hi[tid * 9 + f] = hv;
        s_lo[tid * 9 + f] = lv;
    }
    __syncthreads();

    size_t elem_base = (size_t)b * KEXPN + half * 2304;
    const uint4* sh = (const uint4*)s_hi;
    const uint4* sl = (const uint4*)s_lo;
    uint4* dh = (uint4*)(Ah + elem_base);
    uint4* dl = (uint4*)(Al + elem_base);
#pragma unroll 2
    for (int j = tid; j < 288; j += 256) { dh[j] = sh[j]; dl[j] = sl[j]; }
}

// ---------------------------------------------------------------------------
// Combine split-K partials -> bf16 hi/lo (theta)
// ---------------------------------------------------------------------------
__global__ void combine_split_kernel(const float* __restrict__ p0,
                                     const float* __restrict__ p1,
                                     bf16* __restrict__ hi, bf16* __restrict__ lo,
                                     int n) {
    int i = blockIdx.x * blockDim.x + threadIdx.x;
    if (i < n) {
        float v = p0[i] + p1[i];
        bf16 h, l;
        split2(v, h, l);
        hi[i] = h; lo[i] = l;
    }
}

// ---------------------------------------------------------------------------
// Weight pack + split into [N][K] bf16 hi/lo, smem transpose tile (32x32)
// ---------------------------------------------------------------------------
__global__ __launch_bounds__(256) void prepw_kernel(
    const float* __restrict__ coef, const float* __restrict__ sb,
    const float* __restrict__ ssp,
    bf16* __restrict__ Wh, bf16* __restrict__ Wl, int N) {
    extern __shared__ __align__(16) char psm[];
    bf16* s_hi = (bf16*)psm;              // [32][288]
    bf16* s_lo = s_hi + 32 * 288;

    int tid = threadIdx.x;
    int ob0 = blockIdx.x * 32;
    int ib0 = blockIdx.y * 32;

    for (int t = tid; t < 32 * 32; t += 256) {
        int i_l = t >> 5, o_l = t & 31;
        int i = ib0 + i_l, o = ob0 + o_l;
        size_t idx = (size_t)i * N + o;
        float s   = ssp[idx];
        float sbv = sb[idx];
        const float4* cp = (const float4*)(coef + idx * NCOEFN);
        float4 c0 = cp[0], c1 = cp[1];
        float cv[8] = {c0.x, c0.y, c0.z, c0.w, c1.x, c1.y, c1.z, c1.w};
        bf16* rh = s_hi + o_l * 288 + i_l * 9;
        bf16* rl = s_lo + o_l * 288 + i_l * 9;
        bf16 hv, lv;
        split2(sbv, hv, lv); rh[0] = hv; rl[0] = lv;
#pragma unroll
        for (int k = 0; k < 8; k++) {
            split2(cv[k] * s, hv, lv);
            rh[1 + k] = hv; rl[1 + k] = lv;
        }
    }
    __syncthreads();

    for (int j = tid; j < 32 * 36; j += 256) {
        int o_l = j / 36, q = j - o_l * 36;
        size_t ebase = (size_t)(ob0 + o_l) * KEXPN + (size_t)ib0 * 9;
        ((uint4*)(Wh + ebase))[q] = ((const uint4*)(s_hi + o_l * 288))[q];
        ((uint4*)(Wl + ebase))[q] = ((const uint4*)(s_lo + o_l * 288))[q];
    }
}

// ---------------------------------------------------------------------------
// Seasonal basis (double trig), combined [640][128] layout, bf16 split
// ---------------------------------------------------------------------------
__global__ void basis_kernel(bf16* Sbh, bf16* Sbl, bf16* Sfh, bf16* Sfl) {
    int idx = blockIdx.x * blockDim.x + threadIdx.x;
    const double step = (639.0 / 640.0) / 639.0;
    const double TWO_PI = 6.283185307179586476925286766559;
    int total_b = BACKN * THN;
    int total_f = FOREN * THN;
    if (idx < total_b) {
        int t = idx / THN, r = idx % THN;
        double lin = (double)t * step;
        int rr = (r < 64) ? r : r - 64;
        double f = (rr == 63) ? 640.0 : (double)rr * (640.0 / 63.0);
        double a = TWO_PI * f * lin;
        bf16 hv, lv;
        split2((float)((r < 64) ? cos(a) : sin(a)), hv, lv);
        Sbh[idx] = hv; Sbl[idx] = lv;
    } else if (idx < total_b + total_f) {
        int j = idx - total_b;
        int t = j / THN, r = j % THN;
        int tt = t + BACKN;
        double lin = (tt == 639) ? (639.0 / 640.0) : (double)tt * step;
        int rr = (r < 64) ? r : r - 64;
        double f = (rr == 63) ? 640.0 : (double)rr * (640.0 / 63.0);
        double a = TWO_PI * f * lin;
        bf16 hv, lv;
        split2((float)((r < 64) ? cos(a) : sin(a)), hv, lv);
        Sfh[j] = hv; Sfl[j] = lv;
    }
}

// ---------------------------------------------------------------------------
// Launch: two half-batch pipelines with a MINIMAL skew (half-1 waits only on
// half-0's first expand) so each half's expand overlaps the other's GEMM.
// prepw + basis on low-priority side stream s2.
// ---------------------------------------------------------------------------
extern "C" void kernel_launch(void* const* d_in, const int* in_sizes, int n_in,
                              void* d_out, int out_size) {
    (void)in_sizes; (void)n_in; (void)out_size;
    const float* x       = (const float*)d_in[0];
    const float* coef_fc = (const float*)d_in[1];
    const float* sb_fc   = (const float*)d_in[2];
    const float* ssp_fc  = (const float*)d_in[3];
    const float* coef_th = (const float*)d_in[4];
    const float* sb_th   = (const float*)d_in[5];
    const float* ssp_th  = (const float*)d_in[6];
    float* out = (float*)d_out;

    bf16 *Ah, *Al, *Wh, *Wl, *Thh, *Thl, *Sch, *Scl;
    float *Hbase, *Ptbase;
    cudaGetSymbolAddress((void**)&Ah, g_Ah);
    cudaGetSymbolAddress((void**)&Al, g_Al);
    cudaGetSymbolAddress((void**)&Wh, g_Wh);
    cudaGetSymbolAddress((void**)&Wl, g_Wl);
    cudaGetSymbolAddress((void**)&Hbase, g_H);
    cudaGetSymbolAddress((void**)&Ptbase, g_Pt);
    cudaGetSymbolAddress((void**)&Thh, g_Thh);
    cudaGetSymbolAddress((void**)&Thl, g_Thl);
    cudaGetSymbolAddress((void**)&Sch, g_Sch);
    cudaGetSymbolAddress((void**)&Scl, g_Scl);

    const size_t WSLICE  = (size_t)KEXPN * UNITSN;
    const size_t WOFF_TH = 4 * WSLICE;
    const size_t PZS_FC  = (size_t)NB * UNITSN;    // z-stride for FC partials
    const size_t PZS_TH  = (size_t)NB * THN;       // z-stride for theta partials

    const int SMEM_FC = 2 * (2 * 128 * 128 + 2 * 64 * 128);   // 96 KB
    const int SMEM_TH = 2 * (2 * 64 * 128 + 2 * 32 * 128);    // 48 KB
    const int SMEM_PW = 2 * 32 * 288 * 2;                     // 36 KB
    cudaFuncSetAttribute((const void*)gemm_mma<128, 64, 32, 32, 0>,
                         cudaFuncAttributeMaxDynamicSharedMemorySize, SMEM_FC);
    cudaFuncSetAttribute((const void*)gemm_mma<128, 64, 32, 32, 2>,
                         cudaFuncAttributeMaxDynamicSharedMemorySize, SMEM_FC);
    cudaFuncSetAttribute((const void*)gemm_mma<64, 32, 16, 16, 0>,
                         cudaFuncAttributeMaxDynamicSharedMemorySize, SMEM_TH);
    cudaFuncSetAttribute((const void*)prepw_kernel,
                         cudaFuncAttributeMaxDynamicSharedMemorySize, SMEM_PW);

    cudaStream_t s2 = g_ss.s2;
    cudaStream_t s3 = g_ss.s3;

    // ---- fork side streams ----
    cudaEventRecord(g_ss.evFork, 0);
    cudaStreamWaitEvent(s2, g_ss.evFork, 0);
    cudaStreamWaitEvent(s3, g_ss.evFork, 0);

    // s2: weight packs + basis
    for (int l = 0; l < NLN; l++) {
        prepw_kernel<<<dim3(UNITSN / 32, UNITSN / 32), 256, SMEM_PW, s2>>>(
            coef_fc + (size_t)l * UNITSN * UNITSN * NCOEFN,
            sb_fc  + (size_t)l * UNITSN * UNITSN,
            ssp_fc + (size_t)l * UNITSN * UNITSN,
            Wh + l * WSLICE, Wl + l * WSLICE, UNITSN);
        cudaEventRecord(g_ss.evW[l], s2);
    }
    prepw_kernel<<<dim3(THN / 32, UNITSN / 32), 256, SMEM_PW, s2>>>(
        coef_th, sb_th, ssp_th, Wh + WOFF_TH, Wl + WOFF_TH, THN);
    cudaEventRecord(g_ss.evW[4], s2);
    {
        int total = BACKN * THN + FOREN * THN;
        basis_kernel<<<(total + 255) / 256, 256, 0, s2>>>(
            Sch, Scl, Sch + (size_t)BACKN * THN, Scl + (size_t)BACKN * THN);
        cudaEventRecord(g_ss.evB, s2);
    }

    // ---- two half-batch pipelines, minimally skewed ----
    for (int h = 0; h < 2; ++h) {
        cudaStream_t st = (h == 0) ? (cudaStream_t)0 : s3;
        const float* xh  = x + (size_t)h * HB * UNITSN;
        bf16* Ahh = Ah + (size_t)h * HB * KEXPN;
        bf16* Alh = Al + (size_t)h * HB * KEXPN;
        float* P0h  = Hbase  + (size_t)h * HB * UNITSN;   // FC partial z=0
        float* P1h  = P0h + PZS_FC;                       // FC partial z=1
        float* Pt0h = Ptbase + (size_t)h * HB * THN;      // theta partial z=0
        float* Pt1h = Pt0h + PZS_TH;                      // theta partial z=1
        bf16* Thhh = Thh + (size_t)h * HB * THN;
        bf16* Thlh = Thl + (size_t)h * HB * THN;

        // minimal skew: half-1 starts after half-0's FIRST EXPAND only
        if (h == 1) cudaStreamWaitEvent(st, g_ss.evE0, 0);

        // FC chain
        const float* hin0 = xh;
        const float* hin1 = nullptr;
        for (int l = 0; l < NLN; l++) {
            expand_kernel<<<HB * 2, 256, 0, st>>>(hin0, hin1, Ahh, Alh);
            if (h == 0 && l == 0) cudaEventRecord(g_ss.evE0, st);
            cudaStreamWaitEvent(st, g_ss.evW[l], 0);
            gemm_mma<128, 64, 32, 32, 0>
                <<<dim3(UNITSN / 64, HB / 128, 2), 256, SMEM_FC, st>>>(
                Ahh, Alh, Wh + l * WSLICE, Wl + l * WSLICE, P0h, nullptr,
                HB, UNITSN, KEXPN / 2, KEXPN, UNITSN, (int)PZS_FC, UNITSN);
            hin0 = P0h; hin1 = P1h;
        }

        // theta layer (512 -> 128), split-K=2 into dedicated g_Pt
        expand_kernel<<<HB * 2, 256, 0, st>>>(hin0, hin1, Ahh, Alh);
        cudaStreamWaitEvent(st, g_ss.evW[4], 0);
        gemm_mma<64, 32, 16, 16, 0>
            <<<dim3(THN / 32, HB / 64, 2), 256, SMEM_TH, st>>>(
            Ahh, Alh, Wh + WOFF_TH, Wl + WOFF_TH, Pt0h, nullptr,
            HB, THN, KEXPN / 2, KEXPN, THN, (int)PZS_TH, THN);
        combine_split_kernel<<<(HB * THN + 255) / 256, 256, 0, st>>>(
            Pt0h, Pt1h, Thhh, Thlh, HB * THN);

        // backcast + forecast merged: theta @ [Sb|Sf] (N=640, K=128)
        cudaStreamWaitEvent(st, g_ss.evB, 0);
        gemm_mma<128, 64, 32, 32, 2>
            <<<dim3((BACKN + FOREN) / 64, HB / 128, 1), 256, SMEM_FC, st>>>(
            Thhh, Thlh, Sch, Scl,
            out + (size_t)h * HB * BACKN,
            out + (size_t)NB * BACKN + (size_t)h * HB * FOREN,
            HB, BACKN + FOREN, THN, THN, BACKN, FOREN, BACKN);
    }

    // ---- join s3 back into the capture origin stream ----
    cudaEventRecord(g_ss.evJoin, s3);
    cudaStreamWaitEvent((cudaStream_t)0, g_ss.evJoin, 0);
}

// round 15
// speedup vs baseline: 1.0658x; 1.0307x over previous
#include <cuda_runtime.h>
#include <cuda_bf16.h>
#include <math.h>
#include <stdint.h>

typedef __nv_bfloat16 bf16;

#define NB     2048
#define HB     1024            // half batch
#define BACKN  512
#define UNITSN 512
#define FOREN  128
#define THN    128
#define NLN    4
#define NCOEFN 8
#define KEXPN  (UNITSN * 9)   // 4608

#define WTOT   ((size_t)KEXPN * (4 * UNITSN + THN))

// ---------------------------------------------------------------------------
// Scratch (static device globals)
// ---------------------------------------------------------------------------
__device__ __align__(16) bf16  g_Ah[(size_t)NB * KEXPN];
__device__ __align__(16) bf16  g_Al[(size_t)NB * KEXPN];
__device__ __align__(16) bf16  g_Wh[WTOT];                     // per-layer slices
__device__ __align__(16) bf16  g_Wl[WTOT];
__device__ __align__(16) float g_H[2][(size_t)NB * UNITSN];    // FC split-K partials
__device__ __align__(16) float g_Pt[2][(size_t)NB * THN];      // theta split-K partials
__device__ __align__(16) bf16  g_Thh[(size_t)NB * THN];
__device__ __align__(16) bf16  g_Thl[(size_t)NB * THN];
__device__ __align__(16) bf16  g_Sch[(BACKN + FOREN) * THN];   // [t(640)][th]
__device__ __align__(16) bf16  g_Scl[(BACKN + FOREN) * THN];

// ---------------------------------------------------------------------------
// Streams + events (static-init: no mem delta during the run)
// s2 = weight prep (lowest priority), s3 = second batch-half pipeline.
// ---------------------------------------------------------------------------
struct SideStream {
    cudaStream_t s2, s3;
    cudaEvent_t evFork, evW[5], evB, evJoin;
    SideStream() {
        int lo = 0, hi = 0;
        cudaDeviceGetStreamPriorityRange(&lo, &hi);   // lo = least priority
        cudaStreamCreateWithPriority(&s2, cudaStreamNonBlocking, lo);
        cudaStreamCreateWithFlags(&s3, cudaStreamNonBlocking);
        cudaEventCreateWithFlags(&evFork, cudaEventDisableTiming);
        for (int i = 0; i < 5; i++)
            cudaEventCreateWithFlags(&evW[i], cudaEventDisableTiming);
        cudaEventCreateWithFlags(&evB, cudaEventDisableTiming);
        cudaEventCreateWithFlags(&evJoin, cudaEventDisableTiming);
    }
};
static SideStream g_ss;

// ---------------------------------------------------------------------------
// PTX helpers (arch-generic, sm_80-level)
// ---------------------------------------------------------------------------
__device__ __forceinline__ uint32_t smem_u32(const void* p) {
    uint32_t a;
    asm("{ .reg .u64 t; cvta.to.shared.u64 t, %1; cvt.u32.u64 %0, t; }"
        : "=r"(a) : "l"(p));
    return a;
}
__device__ __forceinline__ void cp16(uint32_t dst, const void* src) {
    asm volatile("cp.async.cg.shared.global [%0], [%1], 16;" :: "r"(dst), "l"(src));
}
__device__ __forceinline__ void cp_commit() {
    asm volatile("cp.async.commit_group;" ::: "memory");
}
template <int N_>
__device__ __forceinline__ void cp_wait() {
    asm volatile("cp.async.wait_group %0;" :: "n"(N_) : "memory");
}
__device__ __forceinline__ void ldsm_x4(uint32_t* r, uint32_t addr) {
    asm volatile("ldmatrix.sync.aligned.m8n8.x4.shared.b16 {%0,%1,%2,%3}, [%4];"
        : "=r"(r[0]), "=r"(r[1]), "=r"(r[2]), "=r"(r[3]) : "r"(addr));
}
__device__ __forceinline__ void mma16816(float* c, const uint32_t* a, const uint32_t* b) {
    asm volatile(
        "mma.sync.aligned.m16n8k16.row.col.f32.bf16.bf16.f32 "
        "{%0,%1,%2,%3}, {%4,%5,%6,%7}, {%8,%9}, {%0,%1,%2,%3};"
        : "+f"(c[0]), "+f"(c[1]), "+f"(c[2]), "+f"(c[3])
        : "r"(a[0]), "r"(a[1]), "r"(a[2]), "r"(a[3]), "r"(b[0]), "r"(b[1]));
}

// smem addressing: 128B rows (BK=64 bf16), 8x16B chunks, SW128-style XOR
__device__ __forceinline__ uint32_t swz(int row, int c) {
    return (uint32_t)(row * 128 + ((c ^ (row & 7)) << 4));
}

__device__ __forceinline__ void split2(float x, bf16& h, bf16& l) {
    h = __float2bfloat16(x);
    l = __float2bfloat16(x - __bfloat162float(h));
}

// ---------------------------------------------------------------------------
// mma.sync GEMM: C = (Ah+Al)[M,Kstride] @ (Bh+Bl)^T  (B stored [N][Kstride])
// Per-CTA K-range [z*K, z*K+K).
// EPI 0: split-K partial -> C + z*ZOFF (ZOFF passed in N2), row stride NS1.
// EPI 2: two-region float remap (z grid = 1).
// BK=64, 2-stage cp.async, 2 CTAs/SM, 3-term bf16 split, fp32 accum.
// ---------------------------------------------------------------------------
template <int BM, int BN, int WM, int WN, int EPI>
__global__ __launch_bounds__(256, 2) void gemm_mma(
    const bf16* __restrict__ Ah, const bf16* __restrict__ Al,
    const bf16* __restrict__ Bh, const bf16* __restrict__ Bl,
    float* __restrict__ C, float* __restrict__ C2,
    int M, int N, int K, int Kstride, int NS1, int N2, int nsplit)
{
    constexpr int BK     = 64;
    constexpr int ROWB   = BK * 2;
    constexpr int ABYTES = BM * ROWB;
    constexpr int BBYTES = BN * ROWB;
    constexpr int STAGE  = 2 * ABYTES + 2 * BBYTES;
    constexpr int MT = WM / 16;
    constexpr int NP = WN / 16;
    static_assert((BM / WM) * (BN / WN) == 8, "8 warps");

    extern __shared__ __align__(16) char smem[];

    const int tid  = threadIdx.x;
    const int wid  = tid >> 5;
    const int lane = tid & 31;
    constexpr int WNN = BN / WN;
    const int wm = wid / WNN, wn = wid % WNN;
    const int bm = blockIdx.y * BM, bn = blockIdx.x * BN;
    const int kbase = blockIdx.z * K;
    const uint32_t sbase = smem_u32(smem);
    const int KCH = K >> 6;

    auto load_stage = [&](int s, int c) {
        uint32_t st = sbase + s * STAGE;
        int k0 = kbase + c * BK;
#pragma unroll 2
        for (int idx = tid; idx < BM * 8; idx += 256) {
            int r = idx >> 3, ch = idx & 7;
            size_t g = (size_t)(bm + r) * Kstride + k0 + ch * 8;
            cp16(st + swz(r, ch), Ah + g);
            cp16(st + ABYTES + swz(r, ch), Al + g);
        }
#pragma unroll 2
        for (int idx = tid; idx < BN * 8; idx += 256) {
            int r = idx >> 3, ch = idx & 7;
            size_t g = (size_t)(bn + r) * Kstride + k0 + ch * 8;
            cp16(st + 2 * ABYTES + swz(r, ch), Bh + g);
            cp16(st + 2 * ABYTES + BBYTES + swz(r, ch), Bl + g);
        }
        cp_commit();
    };

    float acc[MT][NP * 2][4];
#pragma unroll
    for (int i = 0; i < MT; i++)
#pragma unroll
        for (int j = 0; j < NP * 2; j++)
#pragma unroll
            for (int q = 0; q < 4; q++) acc[i][j][q] = 0.0f;

    uint32_t ah[2][MT][4], al[2][MT][4], bh[2][NP][4], bl[2][NP][4];

    const int a_row0 = wm * WM + (lane & 15);
    const int a_sel  = lane >> 4;
    const int b_row0 = wn * WN + (lane & 7) + ((lane & 16) >> 1);
    const int b_sel  = (lane >> 3) & 1;

    auto ld_frags = [&](int buf, uint32_t st, int ks) {
#pragma unroll
        for (int mt = 0; mt < MT; ++mt) {
            int row = a_row0 + mt * 16;
            int ch  = ks * 2 + a_sel;
            ldsm_x4(ah[buf][mt], st + swz(row, ch));
            ldsm_x4(al[buf][mt], st + ABYTES + swz(row, ch));
        }
#pragma unroll
        for (int p = 0; p < NP; ++p) {
            int row = b_row0 + p * 16;
            int ch  = ks * 2 + b_sel;
            ldsm_x4(bh[buf][p], st + 2 * ABYTES + swz(row, ch));
            ldsm_x4(bl[buf][p], st + 2 * ABYTES + BBYTES + swz(row, ch));
        }
    };
    auto do_mma = [&](int buf) {
#pragma unroll
        for (int t = 0; t < 3; ++t)
#pragma unroll
            for (int mt = 0; mt < MT; ++mt)
#pragma unroll
                for (int p = 0; p < NP; ++p) {
                    const uint32_t* af = (t == 2) ? al[buf][mt] : ah[buf][mt];
                    const uint32_t* bf = (t == 1) ? bl[buf][p]  : bh[buf][p];
                    mma16816(acc[mt][2 * p],     af, bf);
                    mma16816(acc[mt][2 * p + 1], af, bf + 2);
                }
    };

    load_stage(0, 0);

    for (int c = 0; c < KCH; ++c) {
        cp_wait<0>();
        __syncthreads();
        uint32_t st = sbase + (c & 1) * STAGE;
        ld_frags(0, st, 0);
        if (c + 1 < KCH) load_stage((c + 1) & 1, c + 1);
        else cp_commit();
#pragma unroll
        for (int ks = 0; ks < 4; ++ks) {
            if (ks < 3) ld_frags((ks + 1) & 1, st, ks + 1);
            do_mma(ks & 1);
        }
    }

    // ---- epilogue ----
    float* Cw;
    int Nw = NS1;
    int bnw = bn;
    if (EPI == 0) {
        Cw = C + (size_t)blockIdx.z * (size_t)N2;   // N2 = z-stride (elements)
    } else {
        Cw = C;
        if (bn >= nsplit) { Cw = C2; Nw = N2; bnw = bn - nsplit; }
    }
#pragma unroll
    for (int mt = 0; mt < MT; ++mt) {
        int m0 = bm + wm * WM + mt * 16 + (lane >> 2);
#pragma unroll
        for (int nt = 0; nt < NP * 2; ++nt) {
            int n0 = bnw + wn * WN + nt * 8 + (lane & 3) * 2;
            *(float2*)(Cw + (size_t)m0 * Nw + n0)       = make_float2(acc[mt][nt][0], acc[mt][nt][1]);
            *(float2*)(Cw + (size_t)(m0 + 8) * Nw + n0) = make_float2(acc[mt][nt][2], acc[mt][nt][3]);
        }
    }
}

// ---------------------------------------------------------------------------
// Expansion (closed-form uniform cubic B-spline) + bf16 split.
// Input h = h0 (+ h1 if non-null): fuses the split-K reduction.
// ---------------------------------------------------------------------------
__global__ __launch_bounds__(256) void expand_kernel(
    const float* __restrict__ h0, const float* __restrict__ h1,
    bf16* __restrict__ Ah, bf16* __restrict__ Al) {
    __shared__ __align__(16) bf16 s_hi[256 * 9];
    __shared__ __align__(16) bf16 s_lo[256 * 9];

    int tid  = threadIdx.x;
    int gid  = blockIdx.x;
    int b    = gid >> 1;
    int half = gid & 1;
    int u    = half * 256 + tid;

    size_t hidx = (size_t)b * UNITSN + u;
    float x = h0[hidx];
    if (h1) x += h1[hidx];

    float vals[9];
    vals[0] = x / (1.0f + expf(-x));
#pragma unroll
    for (int k = 1; k < 9; k++) vals[k] = 0.0f;

    int c = -1;
#pragma unroll
    for (int j = 0; j < 12; j++) {
        float gj = (float)(0.4 * (double)(j - 3) - 1.0);
        c += (x >= gj) ? 1 : 0;
    }
    if (c >= 0 && c <= 10) {
        float gc = (float)c * 0.4f - 2.2f;
        float t  = (x - gc) * 2.5f;
        float t2 = t * t, t3 = t2 * t;
        float omt = 1.0f - t;
        float w0 = t3 * (1.0f / 6.0f);
        float w1 = (1.0f + 3.0f * t + 3.0f * t2 - 3.0f * t3) * (1.0f / 6.0f);
        float w2 = (4.0f - 6.0f * t2 + 3.0f * t3) * (1.0f / 6.0f);
        float w3 = omt * omt * omt * (1.0f / 6.0f);
        if (c <= 7)                    vals[1 + c]   = w0;
        if (c - 1 >= 0 && c - 1 <= 7)  vals[c]       = w1;
        if (c - 2 >= 0 && c - 2 <= 7)  vals[c - 1]   = w2;
        if (c - 3 >= 0)                vals[c - 2]   = w3;
    }

#pragma unroll
    for (int f = 0; f < 9; f++) {
        bf16 hv, lv;
        split2(vals[f], hv, lv);
        s_hi[tid * 9 + f] = hv;
        s_lo[tid * 9 + f] = lv;
    }
    __syncthreads();

    size_t elem_base = (size_t)b * KEXPN + half * 2304;
    const uint4* sh = (const uint4*)s_hi;
    const uint4* sl = (const uint4*)s_lo;
    uint4* dh = (uint4*)(Ah + elem_base);
    uint4* dl = (uint4*)(Al + elem_base);
#pragma unroll 2
    for (int j = tid; j < 288; j += 256) { dh[j] = sh[j]; dl[j] = sl[j]; }
}

// ---------------------------------------------------------------------------
// Combine split-K partials -> bf16 hi/lo (theta), vectorized 2 elems/thread
// ---------------------------------------------------------------------------
__global__ void combine_split_kernel(const float* __restrict__ p0,
                                     const float* __restrict__ p1,
                                     bf16* __restrict__ hi, bf16* __restrict__ lo,
                                     int n) {
    int i = (blockIdx.x * blockDim.x + threadIdx.x) * 2;
    if (i < n) {
        float2 a = *(const float2*)(p0 + i);
        float2 b = *(const float2*)(p1 + i);
        float v0 = a.x + b.x, v1 = a.y + b.y;
        bf16 h0, l0, h1, l1;
        split2(v0, h0, l0);
        split2(v1, h1, l1);
        __nv_bfloat162 hv; hv.x = h0; hv.y = h1;
        __nv_bfloat162 lv; lv.x = l0; lv.y = l1;
        *(__nv_bfloat162*)(hi + i) = hv;
        *(__nv_bfloat162*)(lo + i) = lv;
    }
}

// ---------------------------------------------------------------------------
// Weight pack + split into [N][K] bf16 hi/lo, smem transpose tile (32x32)
// ---------------------------------------------------------------------------
__global__ __launch_bounds__(256) void prepw_kernel(
    const float* __restrict__ coef, const float* __restrict__ sb,
    const float* __restrict__ ssp,
    bf16* __restrict__ Wh, bf16* __restrict__ Wl, int N) {
    extern __shared__ __align__(16) char psm[];
    bf16* s_hi = (bf16*)psm;              // [32][288]
    bf16* s_lo = s_hi + 32 * 288;

    int tid = threadIdx.x;
    int ob0 = blockIdx.x * 32;
    int ib0 = blockIdx.y * 32;

    for (int t = tid; t < 32 * 32; t += 256) {
        int i_l = t >> 5, o_l = t & 31;
        int i = ib0 + i_l, o = ob0 + o_l;
        size_t idx = (size_t)i * N + o;
        float s   = ssp[idx];
        float sbv = sb[idx];
        const float4* cp = (const float4*)(coef + idx * NCOEFN);
        float4 c0 = cp[0], c1 = cp[1];
        float cv[8] = {c0.x, c0.y, c0.z, c0.w, c1.x, c1.y, c1.z, c1.w};
        bf16* rh = s_hi + o_l * 288 + i_l * 9;
        bf16* rl = s_lo + o_l * 288 + i_l * 9;
        bf16 hv, lv;
        split2(sbv, hv, lv); rh[0] = hv; rl[0] = lv;
#pragma unroll
        for (int k = 0; k < 8; k++) {
            split2(cv[k] * s, hv, lv);
            rh[1 + k] = hv; rl[1 + k] = lv;
        }
    }
    __syncthreads();

    for (int j = tid; j < 32 * 36; j += 256) {
        int o_l = j / 36, q = j - o_l * 36;
        size_t ebase = (size_t)(ob0 + o_l) * KEXPN + (size_t)ib0 * 9;
        ((uint4*)(Wh + ebase))[q] = ((const uint4*)(s_hi + o_l * 288))[q];
        ((uint4*)(Wl + ebase))[q] = ((const uint4*)(s_lo + o_l * 288))[q];
    }
}

// ---------------------------------------------------------------------------
// Seasonal basis (double trig), combined [640][128] layout, bf16 split
// ---------------------------------------------------------------------------
__global__ void basis_kernel(bf16* Sbh, bf16* Sbl, bf16* Sfh, bf16* Sfl) {
    int idx = blockIdx.x * blockDim.x + threadIdx.x;
    const double step = (639.0 / 640.0) / 639.0;
    const double TWO_PI = 6.283185307179586476925286766559;
    int total_b = BACKN * THN;
    int total_f = FOREN * THN;
    if (idx < total_b) {
        int t = idx / THN, r = idx % THN;
        double lin = (double)t * step;
        int rr = (r < 64) ? r : r - 64;
        double f = (rr == 63) ? 640.0 : (double)rr * (640.0 / 63.0);
        double a = TWO_PI * f * lin;
        bf16 hv, lv;
        split2((float)((r < 64) ? cos(a) : sin(a)), hv, lv);
        Sbh[idx] = hv; Sbl[idx] = lv;
    } else if (idx < total_b + total_f) {
        int j = idx - total_b;
        int t = j / THN, r = j % THN;
        int tt = t + BACKN;
        double lin = (tt == 639) ? (639.0 / 640.0) : (double)tt * step;
        int rr = (r < 64) ? r : r - 64;
        double f = (rr == 63) ? 640.0 : (double)rr * (640.0 / 63.0);
        double a = TWO_PI * f * lin;
        bf16 hv, lv;
        split2((float)((r < 64) ? cos(a) : sin(a)), hv, lv);
        Sfh[j] = hv; Sfl[j] = lv;
    }
}

// ---------------------------------------------------------------------------
// Launch: two half-batch pipelines (stream 0 + s3), no skew (R12 layout);
// prepw + basis on low-priority side stream s2. All regions disjoint.
// ---------------------------------------------------------------------------
extern "C" void kernel_launch(void* const* d_in, const int* in_sizes, int n_in,
                              void* d_out, int out_size) {
    (void)in_sizes; (void)n_in; (void)out_size;
    const float* x       = (const float*)d_in[0];
    const float* coef_fc = (const float*)d_in[1];
    const float* sb_fc   = (const float*)d_in[2];
    const float* ssp_fc  = (const float*)d_in[3];
    const float* coef_th = (const float*)d_in[4];
    const float* sb_th   = (const float*)d_in[5];
    const float* ssp_th  = (const float*)d_in[6];
    float* out = (float*)d_out;

    bf16 *Ah, *Al, *Wh, *Wl, *Thh, *Thl, *Sch, *Scl;
    float *Hbase, *Ptbase;
    cudaGetSymbolAddress((void**)&Ah, g_Ah);
    cudaGetSymbolAddress((void**)&Al, g_Al);
    cudaGetSymbolAddress((void**)&Wh, g_Wh);
    cudaGetSymbolAddress((void**)&Wl, g_Wl);
    cudaGetSymbolAddress((void**)&Hbase, g_H);
    cudaGetSymbolAddress((void**)&Ptbase, g_Pt);
    cudaGetSymbolAddress((void**)&Thh, g_Thh);
    cudaGetSymbolAddress((void**)&Thl, g_Thl);
    cudaGetSymbolAddress((void**)&Sch, g_Sch);
    cudaGetSymbolAddress((void**)&Scl, g_Scl);

    const size_t WSLICE  = (size_t)KEXPN * UNITSN;
    const size_t WOFF_TH = 4 * WSLICE;
    const size_t PZS_FC  = (size_t)NB * UNITSN;    // z-stride for FC partials
    const size_t PZS_TH  = (size_t)NB * THN;       // z-stride for theta partials

    const int SMEM_FC = 2 * (2 * 128 * 128 + 2 * 64 * 128);   // 96 KB
    const int SMEM_TH = 2 * (2 * 64 * 128 + 2 * 32 * 128);    // 48 KB
    const int SMEM_PW = 2 * 32 * 288 * 2;                     // 36 KB
    cudaFuncSetAttribute((const void*)gemm_mma<128, 64, 32, 32, 0>,
                         cudaFuncAttributeMaxDynamicSharedMemorySize, SMEM_FC);
    cudaFuncSetAttribute((const void*)gemm_mma<128, 64, 32, 32, 2>,
                         cudaFuncAttributeMaxDynamicSharedMemorySize, SMEM_FC);
    cudaFuncSetAttribute((const void*)gemm_mma<64, 32, 16, 16, 0>,
                         cudaFuncAttributeMaxDynamicSharedMemorySize, SMEM_TH);
    cudaFuncSetAttribute((const void*)prepw_kernel,
                         cudaFuncAttributeMaxDynamicSharedMemorySize, SMEM_PW);

    cudaStream_t s2 = g_ss.s2;
    cudaStream_t s3 = g_ss.s3;

    // ---- fork side streams ----
    cudaEventRecord(g_ss.evFork, 0);
    cudaStreamWaitEvent(s2, g_ss.evFork, 0);
    cudaStreamWaitEvent(s3, g_ss.evFork, 0);

    // s2: weight packs + basis
    for (int l = 0; l < NLN; l++) {
        prepw_kernel<<<dim3(UNITSN / 32, UNITSN / 32), 256, SMEM_PW, s2>>>(
            coef_fc + (size_t)l * UNITSN * UNITSN * NCOEFN,
            sb_fc  + (size_t)l * UNITSN * UNITSN,
            ssp_fc + (size_t)l * UNITSN * UNITSN,
            Wh + l * WSLICE, Wl + l * WSLICE, UNITSN);
        cudaEventRecord(g_ss.evW[l], s2);
    }
    prepw_kernel<<<dim3(THN / 32, UNITSN / 32), 256, SMEM_PW, s2>>>(
        coef_th, sb_th, ssp_th, Wh + WOFF_TH, Wl + WOFF_TH, THN);
    cudaEventRecord(g_ss.evW[4], s2);
    {
        int total = BACKN * THN + FOREN * THN;
        basis_kernel<<<(total + 255) / 256, 256, 0, s2>>>(
            Sch, Scl, Sch + (size_t)BACKN * THN, Scl + (size_t)BACKN * THN);
        cudaEventRecord(g_ss.evB, s2);
    }

    // ---- two half-batch pipelines ----
    for (int h = 0; h < 2; ++h) {
        cudaStream_t st = (h == 0) ? (cudaStream_t)0 : s3;
        const float* xh  = x + (size_t)h * HB * UNITSN;
        bf16* Ahh = Ah + (size_t)h * HB * KEXPN;
        bf16* Alh = Al + (size_t)h * HB * KEXPN;
        float* P0h  = Hbase  + (size_t)h * HB * UNITSN;   // FC partial z=0
        float* P1h  = P0h + PZS_FC;                       // FC partial z=1
        float* Pt0h = Ptbase + (size_t)h * HB * THN;      // theta partial z=0
        float* Pt1h = Pt0h + PZS_TH;                      // theta partial z=1
        bf16* Thhh = Thh + (size_t)h * HB * THN;
        bf16* Thlh = Thl + (size_t)h * HB * THN;

        // FC chain
        const float* hin0 = xh;
        const float* hin1 = nullptr;
        for (int l = 0; l < NLN; l++) {
            expand_kernel<<<HB * 2, 256, 0, st>>>(hin0, hin1, Ahh, Alh);
            cudaStreamWaitEvent(st, g_ss.evW[l], 0);
            gemm_mma<128, 64, 32, 32, 0>
                <<<dim3(UNITSN / 64, HB / 128, 2), 256, SMEM_FC, st>>>(
                Ahh, Alh, Wh + l * WSLICE, Wl + l * WSLICE, P0h, nullptr,
                HB, UNITSN, KEXPN / 2, KEXPN, UNITSN, (int)PZS_FC, UNITSN);
            hin0 = P0h; hin1 = P1h;
        }

        // theta layer (512 -> 128), split-K=2 into dedicated g_Pt
        expand_kernel<<<HB * 2, 256, 0, st>>>(hin0, hin1, Ahh, Alh);
        cudaStreamWaitEvent(st, g_ss.evW[4], 0);
        gemm_mma<64, 32, 16, 16, 0>
            <<<dim3(THN / 32, HB / 64, 2), 256, SMEM_TH, st>>>(
            Ahh, Alh, Wh + WOFF_TH, Wl + WOFF_TH, Pt0h, nullptr,
            HB, THN, KEXPN / 2, KEXPN, THN, (int)PZS_TH, THN);
        combine_split_kernel<<<(HB * THN / 2 + 255) / 256, 256, 0, st>>>(
            Pt0h, Pt1h, Thhh, Thlh, HB * THN);

        // backcast + forecast merged: theta @ [Sb|Sf] (N=640, K=128)
        cudaStreamWaitEvent(st, g_ss.evB, 0);
        gemm_mma<128, 64, 32, 32, 2>
            <<<dim3((BACKN + FOREN) / 64, HB / 128, 1), 256, SMEM_FC, st>>>(
            Thhh, Thlh, Sch, Scl,
            out + (size_t)h * HB * BACKN,
            out + (size_t)NB * BACKN + (size_t)h * HB * FOREN,
            HB, BACKN + FOREN, THN, THN, BACKN, FOREN, BACKN);
    }

    // ---- join s3 back into the capture origin stream ----
    cudaEventRecord(g_ss.evJoin, s3);
    cudaStreamWaitEvent((cudaStream_t)0, g_ss.evJoin, 0);
}

// round 16
// speedup vs baseline: 1.1115x; 1.0429x over previous
#include <cuda_runtime.h>
#include <cuda_bf16.h>
#include <math.h>
#include <stdint.h>

typedef __nv_bfloat16 bf16;

#define NB     2048
#define HB     1024            // half batch
#define BACKN  512
#define UNITSN 512
#define FOREN  128
#define THN    128
#define NLN    4
#define NCOEFN 8
#define KEXPN  (UNITSN * 9)   // 4608

#define WTOT   ((size_t)KEXPN * (4 * UNITSN + THN))

// ---------------------------------------------------------------------------
// Scratch (static device globals)
// ---------------------------------------------------------------------------
__device__ __align__(16) bf16  g_Ah[(size_t)NB * KEXPN];
__device__ __align__(16) bf16  g_Al[(size_t)NB * KEXPN];
__device__ __align__(16) bf16  g_Wh[WTOT];                     // per-layer slices
__device__ __align__(16) bf16  g_Wl[WTOT];
__device__ __align__(16) float g_H[2][(size_t)NB * UNITSN];    // FC split-K partials
__device__ __align__(16) float g_Pt[2][(size_t)NB * THN];      // theta split-K partials
__device__ __align__(16) bf16  g_Thh[(size_t)NB * THN];
__device__ __align__(16) bf16  g_Thl[(size_t)NB * THN];
__device__ __align__(16) bf16  g_Sch[(BACKN + FOREN) * THN];   // [t(640)][th]
__device__ __align__(16) bf16  g_Scl[(BACKN + FOREN) * THN];

// ---------------------------------------------------------------------------
// Streams + events (static-init: no mem delta during the run)
// s2 = weight prep (lowest priority), s3 = second batch-half pipeline.
// ---------------------------------------------------------------------------
struct SideStream {
    cudaStream_t s2, s3;
    cudaEvent_t evFork, evW[5], evB, evJoin;
    SideStream() {
        int lo = 0, hi = 0;
        cudaDeviceGetStreamPriorityRange(&lo, &hi);   // lo = least priority
        cudaStreamCreateWithPriority(&s2, cudaStreamNonBlocking, lo);
        cudaStreamCreateWithFlags(&s3, cudaStreamNonBlocking);
        cudaEventCreateWithFlags(&evFork, cudaEventDisableTiming);
        for (int i = 0; i < 5; i++)
            cudaEventCreateWithFlags(&evW[i], cudaEventDisableTiming);
        cudaEventCreateWithFlags(&evB, cudaEventDisableTiming);
        cudaEventCreateWithFlags(&evJoin, cudaEventDisableTiming);
    }
};
static SideStream g_ss;

// ---------------------------------------------------------------------------
// PTX helpers (arch-generic, sm_80-level)
// ---------------------------------------------------------------------------
__device__ __forceinline__ uint32_t smem_u32(const void* p) {
    uint32_t a;
    asm("{ .reg .u64 t; cvta.to.shared.u64 t, %1; cvt.u32.u64 %0, t; }"
        : "=r"(a) : "l"(p));
    return a;
}
__device__ __forceinline__ void cp16(uint32_t dst, const void* src) {
    asm volatile("cp.async.cg.shared.global [%0], [%1], 16;" :: "r"(dst), "l"(src));
}
__device__ __forceinline__ void cp_commit() {
    asm volatile("cp.async.commit_group;" ::: "memory");
}
template <int N_>
__device__ __forceinline__ void cp_wait() {
    asm volatile("cp.async.wait_group %0;" :: "n"(N_) : "memory");
}
__device__ __forceinline__ void ldsm_x4(uint32_t* r, uint32_t addr) {
    asm volatile("ldmatrix.sync.aligned.m8n8.x4.shared.b16 {%0,%1,%2,%3}, [%4];"
        : "=r"(r[0]), "=r"(r[1]), "=r"(r[2]), "=r"(r[3]) : "r"(addr));
}
__device__ __forceinline__ void mma16816(float* c, const uint32_t* a, const uint32_t* b) {
    asm volatile(
        "mma.sync.aligned.m16n8k16.row.col.f32.bf16.bf16.f32 "
        "{%0,%1,%2,%3}, {%4,%5,%6,%7}, {%8,%9}, {%0,%1,%2,%3};"
        : "+f"(c[0]), "+f"(c[1]), "+f"(c[2]), "+f"(c[3])
        : "r"(a[0]), "r"(a[1]), "r"(a[2]), "r"(a[3]), "r"(b[0]), "r"(b[1]));
}

// smem addressing: 128B rows (BK=64 bf16), 8x16B chunks, SW128-style XOR
__device__ __forceinline__ uint32_t swz(int row, int c) {
    return (uint32_t)(row * 128 + ((c ^ (row & 7)) << 4));
}

__device__ __forceinline__ void split2(float x, bf16& h, bf16& l) {
    h = __float2bfloat16(x);
    l = __float2bfloat16(x - __bfloat162float(h));
}

// ---------------------------------------------------------------------------
// mma.sync GEMM: C = (Ah+Al)[M,Kstride] @ (Bh+Bl)^T  (B stored [N][Kstride])
// Per-CTA K-range [z*K, z*K+K).
// EPI 0: split-K partial -> C + z*ZOFF (ZOFF passed in N2), row stride NS1.
// EPI 2: two-region float remap (z grid = 1).
// BK=64, 2-stage cp.async, 2 CTAs/SM, 3-term bf16 split, fp32 accum.
// ---------------------------------------------------------------------------
template <int BM, int BN, int WM, int WN, int EPI>
__global__ __launch_bounds__(256, 2) void gemm_mma(
    const bf16* __restrict__ Ah, const bf16* __restrict__ Al,
    const bf16* __restrict__ Bh, const bf16* __restrict__ Bl,
    float* __restrict__ C, float* __restrict__ C2,
    int M, int N, int K, int Kstride, int NS1, int N2, int nsplit)
{
    constexpr int BK     = 64;
    constexpr int ROWB   = BK * 2;
    constexpr int ABYTES = BM * ROWB;
    constexpr int BBYTES = BN * ROWB;
    constexpr int STAGE  = 2 * ABYTES + 2 * BBYTES;
    constexpr int MT = WM / 16;
    constexpr int NP = WN / 16;
    static_assert((BM / WM) * (BN / WN) == 8, "8 warps");

    extern __shared__ __align__(16) char smem[];

    const int tid  = threadIdx.x;
    const int wid  = tid >> 5;
    const int lane = tid & 31;
    constexpr int WNN = BN / WN;
    const int wm = wid / WNN, wn = wid % WNN;
    const int bm = blockIdx.y * BM, bn = blockIdx.x * BN;
    const int kbase = blockIdx.z * K;
    const uint32_t sbase = smem_u32(smem);
    const int KCH = K >> 6;

    auto load_stage = [&](int s, int c) {
        uint32_t st = sbase + s * STAGE;
        int k0 = kbase + c * BK;
#pragma unroll 2
        for (int idx = tid; idx < BM * 8; idx += 256) {
            int r = idx >> 3, ch = idx & 7;
            size_t g = (size_t)(bm + r) * Kstride + k0 + ch * 8;
            cp16(st + swz(r, ch), Ah + g);
            cp16(st + ABYTES + swz(r, ch), Al + g);
        }
#pragma unroll 2
        for (int idx = tid; idx < BN * 8; idx += 256) {
            int r = idx >> 3, ch = idx & 7;
            size_t g = (size_t)(bn + r) * Kstride + k0 + ch * 8;
            cp16(st + 2 * ABYTES + swz(r, ch), Bh + g);
            cp16(st + 2 * ABYTES + BBYTES + swz(r, ch), Bl + g);
        }
        cp_commit();
    };

    float acc[MT][NP * 2][4];
#pragma unroll
    for (int i = 0; i < MT; i++)
#pragma unroll
        for (int j = 0; j < NP * 2; j++)
#pragma unroll
            for (int q = 0; q < 4; q++) acc[i][j][q] = 0.0f;

    uint32_t ah[2][MT][4], al[2][MT][4], bh[2][NP][4], bl[2][NP][4];

    const int a_row0 = wm * WM + (lane & 15);
    const int a_sel  = lane >> 4;
    const int b_row0 = wn * WN + (lane & 7) + ((lane & 16) >> 1);
    const int b_sel  = (lane >> 3) & 1;

    auto ld_frags = [&](int buf, uint32_t st, int ks) {
#pragma unroll
        for (int mt = 0; mt < MT; ++mt) {
            int row = a_row0 + mt * 16;
            int ch  = ks * 2 + a_sel;
            ldsm_x4(ah[buf][mt], st + swz(row, ch));
            ldsm_x4(al[buf][mt], st + ABYTES + swz(row, ch));
        }
#pragma unroll
        for (int p = 0; p < NP; ++p) {
            int row = b_row0 + p * 16;
            int ch  = ks * 2 + b_sel;
            ldsm_x4(bh[buf][p], st + 2 * ABYTES + swz(row, ch));
            ldsm_x4(bl[buf][p], st + 2 * ABYTES + BBYTES + swz(row, ch));
        }
    };
    auto do_mma = [&](int buf) {
#pragma unroll
        for (int t = 0; t < 3; ++t)
#pragma unroll
            for (int mt = 0; mt < MT; ++mt)
#pragma unroll
                for (int p = 0; p < NP; ++p) {
                    const uint32_t* af = (t == 2) ? al[buf][mt] : ah[buf][mt];
                    const uint32_t* bf = (t == 1) ? bl[buf][p]  : bh[buf][p];
                    mma16816(acc[mt][2 * p],     af, bf);
                    mma16816(acc[mt][2 * p + 1], af, bf + 2);
                }
    };

    load_stage(0, 0);

    for (int c = 0; c < KCH; ++c) {
        cp_wait<0>();
        __syncthreads();
        uint32_t st = sbase + (c & 1) * STAGE;
        ld_frags(0, st, 0);
        if (c + 1 < KCH) load_stage((c + 1) & 1, c + 1);
        else cp_commit();
#pragma unroll
        for (int ks = 0; ks < 4; ++ks) {
            if (ks < 3) ld_frags((ks + 1) & 1, st, ks + 1);
            do_mma(ks & 1);
        }
    }

    // ---- epilogue ----
    float* Cw;
    int Nw = NS1;
    int bnw = bn;
    if (EPI == 0) {
        Cw = C + (size_t)blockIdx.z * (size_t)N2;   // N2 = z-stride (elements)
    } else {
        Cw = C;
        if (bn >= nsplit) { Cw = C2; Nw = N2; bnw = bn - nsplit; }
    }
#pragma unroll
    for (int mt = 0; mt < MT; ++mt) {
        int m0 = bm + wm * WM + mt * 16 + (lane >> 2);
#pragma unroll
        for (int nt = 0; nt < NP * 2; ++nt) {
            int n0 = bnw + wn * WN + nt * 8 + (lane & 3) * 2;
            *(float2*)(Cw + (size_t)m0 * Nw + n0)       = make_float2(acc[mt][nt][0], acc[mt][nt][1]);
            *(float2*)(Cw + (size_t)(m0 + 8) * Nw + n0) = make_float2(acc[mt][nt][2], acc[mt][nt][3]);
        }
    }
}

// ---------------------------------------------------------------------------
// Expansion (closed-form uniform cubic B-spline) + bf16 split.
// Input h = h0 (+ h1 if non-null): fuses the split-K reduction.
// ---------------------------------------------------------------------------
__global__ __launch_bounds__(256) void expand_kernel(
    const float* __restrict__ h0, const float* __restrict__ h1,
    bf16* __restrict__ Ah, bf16* __restrict__ Al) {
    __shared__ __align__(16) bf16 s_hi[256 * 9];
    __shared__ __align__(16) bf16 s_lo[256 * 9];

    int tid  = threadIdx.x;
    int gid  = blockIdx.x;
    int b    = gid >> 1;
    int half = gid & 1;
    int u    = half * 256 + tid;

    size_t hidx = (size_t)b * UNITSN + u;
    float x = h0[hidx];
    if (h1) x += h1[hidx];

    float vals[9];
    vals[0] = x / (1.0f + expf(-x));
#pragma unroll
    for (int k = 1; k < 9; k++) vals[k] = 0.0f;

    int c = -1;
#pragma unroll
    for (int j = 0; j < 12; j++) {
        float gj = (float)(0.4 * (double)(j - 3) - 1.0);
        c += (x >= gj) ? 1 : 0;
    }
    if (c >= 0 && c <= 10) {
        float gc = (float)c * 0.4f - 2.2f;
        float t  = (x - gc) * 2.5f;
        float t2 = t * t, t3 = t2 * t;
        float omt = 1.0f - t;
        float w0 = t3 * (1.0f / 6.0f);
        float w1 = (1.0f + 3.0f * t + 3.0f * t2 - 3.0f * t3) * (1.0f / 6.0f);
        float w2 = (4.0f - 6.0f * t2 + 3.0f * t3) * (1.0f / 6.0f);
        float w3 = omt * omt * omt * (1.0f / 6.0f);
        if (c <= 7)                    vals[1 + c]   = w0;
        if (c - 1 >= 0 && c - 1 <= 7)  vals[c]       = w1;
        if (c - 2 >= 0 && c - 2 <= 7)  vals[c - 1]   = w2;
        if (c - 3 >= 0)                vals[c - 2]   = w3;
    }

#pragma unroll
    for (int f = 0; f < 9; f++) {
        bf16 hv, lv;
        split2(vals[f], hv, lv);
        s_hi[tid * 9 + f] = hv;
        s_lo[tid * 9 + f] = lv;
    }
    __syncthreads();

    size_t elem_base = (size_t)b * KEXPN + half * 2304;
    const uint4* sh = (const uint4*)s_hi;
    const uint4* sl = (const uint4*)s_lo;
    uint4* dh = (uint4*)(Ah + elem_base);
    uint4* dl = (uint4*)(Al + elem_base);
#pragma unroll 2
    for (int j = tid; j < 288; j += 256) { dh[j] = sh[j]; dl[j] = sl[j]; }
}

// ---------------------------------------------------------------------------
// Combine split-K partials -> bf16 hi/lo (theta), vectorized 2 elems/thread
// ---------------------------------------------------------------------------
__global__ void combine_split_kernel(const float* __restrict__ p0,
                                     const float* __restrict__ p1,
                                     bf16* __restrict__ hi, bf16* __restrict__ lo,
                                     int n) {
    int i = (blockIdx.x * blockDim.x + threadIdx.x) * 2;
    if (i < n) {
        float2 a = *(const float2*)(p0 + i);
        float2 b = *(const float2*)(p1 + i);
        float v0 = a.x + b.x, v1 = a.y + b.y;
        bf16 h0, l0, h1, l1;
        split2(v0, h0, l0);
        split2(v1, h1, l1);
        __nv_bfloat162 hv; hv.x = h0; hv.y = h1;
        __nv_bfloat162 lv; lv.x = l0; lv.y = l1;
        *(__nv_bfloat162*)(hi + i) = hv;
        *(__nv_bfloat162*)(lo + i) = lv;
    }
}

// ---------------------------------------------------------------------------
// Weight pack + split into [N][K] bf16 hi/lo, smem transpose tile.
// Tile = 32 outputs x 16 i-units (18 KB smem; FC grid = 512 CTAs).
// ---------------------------------------------------------------------------
__global__ __launch_bounds__(256) void prepw_kernel(
    const float* __restrict__ coef, const float* __restrict__ sb,
    const float* __restrict__ ssp,
    bf16* __restrict__ Wh, bf16* __restrict__ Wl, int N) {
    extern __shared__ __align__(16) char psm[];
    bf16* s_hi = (bf16*)psm;              // [32][144]
    bf16* s_lo = s_hi + 32 * 144;

    int tid = threadIdx.x;
    int ob0 = blockIdx.x * 32;
    int ib0 = blockIdx.y * 16;

    for (int t = tid; t < 16 * 32; t += 256) {
        int i_l = t >> 5, o_l = t & 31;
        int i = ib0 + i_l, o = ob0 + o_l;
        size_t idx = (size_t)i * N + o;
        float s   = ssp[idx];
        float sbv = sb[idx];
        const float4* cp = (const float4*)(coef + idx * NCOEFN);
        float4 c0 = cp[0], c1 = cp[1];
        float cv[8] = {c0.x, c0.y, c0.z, c0.w, c1.x, c1.y, c1.z, c1.w};
        bf16* rh = s_hi + o_l * 144 + i_l * 9;
        bf16* rl = s_lo + o_l * 144 + i_l * 9;
        bf16 hv, lv;
        split2(sbv, hv, lv); rh[0] = hv; rl[0] = lv;
#pragma unroll
        for (int k = 0; k < 8; k++) {
            split2(cv[k] * s, hv, lv);
            rh[1 + k] = hv; rl[1 + k] = lv;
        }
    }
    __syncthreads();

    // per output row: 144 bf16 = 288 B = 18 uint4
    for (int j = tid; j < 32 * 18; j += 256) {
        int o_l = j / 18, q = j - o_l * 18;
        size_t ebase = (size_t)(ob0 + o_l) * KEXPN + (size_t)ib0 * 9;
        ((uint4*)(Wh + ebase))[q] = ((const uint4*)(s_hi + o_l * 144))[q];
        ((uint4*)(Wl + ebase))[q] = ((const uint4*)(s_lo + o_l * 144))[q];
    }
}

// ---------------------------------------------------------------------------
// Seasonal basis (double trig), combined [640][128] layout, bf16 split
// ---------------------------------------------------------------------------
__global__ void basis_kernel(bf16* Sbh, bf16* Sbl, bf16* Sfh, bf16* Sfl) {
    int idx = blockIdx.x * blockDim.x + threadIdx.x;
    const double step = (639.0 / 640.0) / 639.0;
    const double TWO_PI = 6.283185307179586476925286766559;
    int total_b = BACKN * THN;
    int total_f = FOREN * THN;
    if (idx < total_b) {
        int t = idx / THN, r = idx % THN;
        double lin = (double)t * step;
        int rr = (r < 64) ? r : r - 64;
        double f = (rr == 63) ? 640.0 : (double)rr * (640.0 / 63.0);
        double a = TWO_PI * f * lin;
        bf16 hv, lv;
        split2((float)((r < 64) ? cos(a) : sin(a)), hv, lv);
        Sbh[idx] = hv; Sbl[idx] = lv;
    } else if (idx < total_b + total_f) {
        int j = idx - total_b;
        int t = j / THN, r = j % THN;
        int tt = t + BACKN;
        double lin = (tt == 639) ? (639.0 / 640.0) : (double)tt * step;
        int rr = (r < 64) ? r : r - 64;
        double f = (rr == 63) ? 640.0 : (double)rr * (640.0 / 63.0);
        double a = TWO_PI * f * lin;
        bf16 hv, lv;
        split2((float)((r < 64) ? cos(a) : sin(a)), hv, lv);
        Sfh[j] = hv; Sfl[j] = lv;
    }
}

// ---------------------------------------------------------------------------
// Launch: two half-batch pipelines (stream 0 + s3), no skew;
// prepw + basis on low-priority side stream s2. All regions disjoint.
// ---------------------------------------------------------------------------
extern "C" void kernel_launch(void* const* d_in, const int* in_sizes, int n_in,
                              void* d_out, int out_size) {
    (void)in_sizes; (void)n_in; (void)out_size;
    const float* x       = (const float*)d_in[0];
    const float* coef_fc = (const float*)d_in[1];
    const float* sb_fc   = (const float*)d_in[2];
    const float* ssp_fc  = (const float*)d_in[3];
    const float* coef_th = (const float*)d_in[4];
    const float* sb_th   = (const float*)d_in[5];
    const float* ssp_th  = (const float*)d_in[6];
    float* out = (float*)d_out;

    bf16 *Ah, *Al, *Wh, *Wl, *Thh, *Thl, *Sch, *Scl;
    float *Hbase, *Ptbase;
    cudaGetSymbolAddress((void**)&Ah, g_Ah);
    cudaGetSymbolAddress((void**)&Al, g_Al);
    cudaGetSymbolAddress((void**)&Wh, g_Wh);
    cudaGetSymbolAddress((void**)&Wl, g_Wl);
    cudaGetSymbolAddress((void**)&Hbase, g_H);
    cudaGetSymbolAddress((void**)&Ptbase, g_Pt);
    cudaGetSymbolAddress((void**)&Thh, g_Thh);
    cudaGetSymbolAddress((void**)&Thl, g_Thl);
    cudaGetSymbolAddress((void**)&Sch, g_Sch);
    cudaGetSymbolAddress((void**)&Scl, g_Scl);

    const size_t WSLICE  = (size_t)KEXPN * UNITSN;
    const size_t WOFF_TH = 4 * WSLICE;
    const size_t PZS_FC  = (size_t)NB * UNITSN;    // z-stride for FC partials
    const size_t PZS_TH  = (size_t)NB * THN;       // z-stride for theta partials

    const int SMEM_FC = 2 * (2 * 128 * 128 + 2 * 64 * 128);   // 96 KB
    const int SMEM_TH = 2 * (2 * 64 * 128 + 2 * 32 * 128);    // 48 KB
    const int SMEM_PW = 2 * 32 * 144 * 2;                     // 18 KB
    cudaFuncSetAttribute((const void*)gemm_mma<128, 64, 32, 32, 0>,
                         cudaFuncAttributeMaxDynamicSharedMemorySize, SMEM_FC);
    cudaFuncSetAttribute((const void*)gemm_mma<128, 64, 32, 32, 2>,
                         cudaFuncAttributeMaxDynamicSharedMemorySize, SMEM_FC);
    cudaFuncSetAttribute((const void*)gemm_mma<64, 32, 16, 16, 0>,
                         cudaFuncAttributeMaxDynamicSharedMemorySize, SMEM_TH);
    cudaFuncSetAttribute((const void*)prepw_kernel,
                         cudaFuncAttributeMaxDynamicSharedMemorySize, SMEM_PW);

    cudaStream_t s2 = g_ss.s2;
    cudaStream_t s3 = g_ss.s3;

    // ---- fork side streams ----
    cudaEventRecord(g_ss.evFork, 0);
    cudaStreamWaitEvent(s2, g_ss.evFork, 0);
    cudaStreamWaitEvent(s3, g_ss.evFork, 0);

    // s2: weight packs + basis
    for (int l = 0; l < NLN; l++) {
        prepw_kernel<<<dim3(UNITSN / 32, UNITSN / 16), 256, SMEM_PW, s2>>>(
            coef_fc + (size_t)l * UNITSN * UNITSN * NCOEFN,
            sb_fc  + (size_t)l * UNITSN * UNITSN,
            ssp_fc + (size_t)l * UNITSN * UNITSN,
            Wh + l * WSLICE, Wl + l * WSLICE, UNITSN);
        cudaEventRecord(g_ss.evW[l], s2);
    }
    prepw_kernel<<<dim3(THN / 32, UNITSN / 16), 256, SMEM_PW, s2>>>(
        coef_th, sb_th, ssp_th, Wh + WOFF_TH, Wl + WOFF_TH, THN);
    cudaEventRecord(g_ss.evW[4], s2);
    {
        int total = BACKN * THN + FOREN * THN;
        basis_kernel<<<(total + 255) / 256, 256, 0, s2>>>(
            Sch, Scl, Sch + (size_t)BACKN * THN, Scl + (size_t)BACKN * THN);
        cudaEventRecord(g_ss.evB, s2);
    }

    // ---- two half-batch pipelines ----
    for (int h = 0; h < 2; ++h) {
        cudaStream_t st = (h == 0) ? (cudaStream_t)0 : s3;
        const float* xh  = x + (size_t)h * HB * UNITSN;
        bf16* Ahh = Ah + (size_t)h * HB * KEXPN;
        bf16* Alh = Al + (size_t)h * HB * KEXPN;
        float* P0h  = Hbase  + (size_t)h * HB * UNITSN;   // FC partial z=0
        float* P1h  = P0h + PZS_FC;                       // FC partial z=1
        float* Pt0h = Ptbase + (size_t)h * HB * THN;      // theta partial z=0
        float* Pt1h = Pt0h + PZS_TH;                      // theta partial z=1
        bf16* Thhh = Thh + (size_t)h * HB * THN;
        bf16* Thlh = Thl + (size_t)h * HB * THN;

        // FC chain
        const float* hin0 = xh;
        const float* hin1 = nullptr;
        for (int l = 0; l < NLN; l++) {
            expand_kernel<<<HB * 2, 256, 0, st>>>(hin0, hin1, Ahh, Alh);
            cudaStreamWaitEvent(st, g_ss.evW[l], 0);
            gemm_mma<128, 64, 32, 32, 0>
                <<<dim3(UNITSN / 64, HB / 128, 2), 256, SMEM_FC, st>>>(
                Ahh, Alh, Wh + l * WSLICE, Wl + l * WSLICE, P0h, nullptr,
                HB, UNITSN, KEXPN / 2, KEXPN, UNITSN, (int)PZS_FC, UNITSN);
            hin0 = P0h; hin1 = P1h;
        }

        // theta layer (512 -> 128), split-K=2 into dedicated g_Pt
        expand_kernel<<<HB * 2, 256, 0, st>>>(hin0, hin1, Ahh, Alh);
        cudaStreamWaitEvent(st, g_ss.evW[4], 0);
        gemm_mma<64, 32, 16, 16, 0>
            <<<dim3(THN / 32, HB / 64, 2), 256, SMEM_TH, st>>>(
            Ahh, Alh, Wh + WOFF_TH, Wl + WOFF_TH, Pt0h, nullptr,
            HB, THN, KEXPN / 2, KEXPN, THN, (int)PZS_TH, THN);
        combine_split_kernel<<<(HB * THN / 2 + 255) / 256, 256, 0, st>>>(
            Pt0h, Pt1h, Thhh, Thlh, HB * THN);

        // backcast + forecast merged: theta @ [Sb|Sf] (N=640, K=128)
        cudaStreamWaitEvent(st, g_ss.evB, 0);
        gemm_mma<128, 64, 32, 32, 2>
            <<<dim3((BACKN + FOREN) / 64, HB / 128, 1), 256, SMEM_FC, st>>>(
            Thhh, Thlh, Sch, Scl,
            out + (size_t)h * HB * BACKN,
            out + (size_t)NB * BACKN + (size_t)h * HB * FOREN,
            HB, BACKN + FOREN, THN, THN, BACKN, FOREN, BACKN);
    }

    // ---- join s3 back into the capture origin stream ----
    cudaEventRecord(g_ss.evJoin, s3);
    cudaStreamWaitEvent((cudaStream_t)0, g_ss.evJoin, 0);
}

// round 17
// speedup vs baseline: 1.1309x; 1.0175x over previous
#include <cuda_runtime.h>
#include <cuda_bf16.h>
#include <math.h>
#include <stdint.h>

typedef __nv_bfloat16 bf16;

#define NB     2048
#define HB     1024            // half batch
#define BACKN  512
#define UNITSN 512
#define FOREN  128
#define THN    128
#define NLN    4
#define NCOEFN 8
#define KEXPN  (UNITSN * 9)   // 4608

#define WTOT   ((size_t)KEXPN * (4 * UNITSN + THN))

// ---------------------------------------------------------------------------
// Scratch (static device globals)
// ---------------------------------------------------------------------------
__device__ __align__(16) bf16  g_Ah[(size_t)NB * KEXPN];
__device__ __align__(16) bf16  g_Al[(size_t)NB * KEXPN];
__device__ __align__(16) bf16  g_Wh[WTOT];                     // per-layer slices
__device__ __align__(16) bf16  g_Wl[WTOT];
__device__ __align__(16) float g_H[2][(size_t)NB * UNITSN];    // FC split-K partials
__device__ __align__(16) float g_Pt[2][(size_t)NB * THN];      // theta split-K partials
__device__ __align__(16) bf16  g_Thh[(size_t)NB * THN];
__device__ __align__(16) bf16  g_Thl[(size_t)NB * THN];
__device__ __align__(16) bf16  g_Sch[(BACKN + FOREN) * THN];   // [t(640)][th]
__device__ __align__(16) bf16  g_Scl[(BACKN + FOREN) * THN];

// ---------------------------------------------------------------------------
// Streams + events (static-init: no mem delta during the run)
// s2 = weight prep (lowest priority), s3 = second batch-half pipeline.
// ---------------------------------------------------------------------------
struct SideStream {
    cudaStream_t s2, s3;
    cudaEvent_t evFork, evW[5], evB, evJoin;
    SideStream() {
        int lo = 0, hi = 0;
        cudaDeviceGetStreamPriorityRange(&lo, &hi);   // lo = least priority
        cudaStreamCreateWithPriority(&s2, cudaStreamNonBlocking, lo);
        cudaStreamCreateWithFlags(&s3, cudaStreamNonBlocking);
        cudaEventCreateWithFlags(&evFork, cudaEventDisableTiming);
        for (int i = 0; i < 5; i++)
            cudaEventCreateWithFlags(&evW[i], cudaEventDisableTiming);
        cudaEventCreateWithFlags(&evB, cudaEventDisableTiming);
        cudaEventCreateWithFlags(&evJoin, cudaEventDisableTiming);
    }
};
static SideStream g_ss;

// ---------------------------------------------------------------------------
// PTX helpers (arch-generic, sm_80-level)
// ---------------------------------------------------------------------------
__device__ __forceinline__ uint32_t smem_u32(const void* p) {
    uint32_t a;
    asm("{ .reg .u64 t; cvta.to.shared.u64 t, %1; cvt.u32.u64 %0, t; }"
        : "=r"(a) : "l"(p));
    return a;
}
__device__ __forceinline__ void cp16(uint32_t dst, const void* src) {
    asm volatile("cp.async.cg.shared.global [%0], [%1], 16;" :: "r"(dst), "l"(src));
}
__device__ __forceinline__ void cp_commit() {
    asm volatile("cp.async.commit_group;" ::: "memory");
}
template <int N_>
__device__ __forceinline__ void cp_wait() {
    asm volatile("cp.async.wait_group %0;" :: "n"(N_) : "memory");
}
__device__ __forceinline__ void ldsm_x4(uint32_t* r, uint32_t addr) {
    asm volatile("ldmatrix.sync.aligned.m8n8.x4.shared.b16 {%0,%1,%2,%3}, [%4];"
        : "=r"(r[0]), "=r"(r[1]), "=r"(r[2]), "=r"(r[3]) : "r"(addr));
}
__device__ __forceinline__ void mma16816(float* c, const uint32_t* a, const uint32_t* b) {
    asm volatile(
        "mma.sync.aligned.m16n8k16.row.col.f32.bf16.bf16.f32 "
        "{%0,%1,%2,%3}, {%4,%5,%6,%7}, {%8,%9}, {%0,%1,%2,%3};"
        : "+f"(c[0]), "+f"(c[1]), "+f"(c[2]), "+f"(c[3])
        : "r"(a[0]), "r"(a[1]), "r"(a[2]), "r"(a[3]), "r"(b[0]), "r"(b[1]));
}

// smem addressing: 128B rows (BK=64 bf16), 8x16B chunks, SW128-style XOR
__device__ __forceinline__ uint32_t swz(int row, int c) {
    return (uint32_t)(row * 128 + ((c ^ (row & 7)) << 4));
}

__device__ __forceinline__ void split2(float x, bf16& h, bf16& l) {
    h = __float2bfloat16(x);
    l = __float2bfloat16(x - __bfloat162float(h));
}

// ---------------------------------------------------------------------------
// mma.sync GEMM: C = (Ah+Al)[M,Kstride] @ (Bh+Bl)^T  (B stored [N][Kstride])
// Per-CTA K-range [z*K, z*K+K).
// EPI 0: split-K partial -> C + z*ZOFF (ZOFF passed in N2), row stride NS1.
// EPI 2: two-region float remap (z grid = 1).
// BK=64, 2-stage cp.async, 2 CTAs/SM, 3-term bf16 split, fp32 accum.
// ---------------------------------------------------------------------------
template <int BM, int BN, int WM, int WN, int EPI>
__global__ __launch_bounds__(256, 2) void gemm_mma(
    const bf16* __restrict__ Ah, const bf16* __restrict__ Al,
    const bf16* __restrict__ Bh, const bf16* __restrict__ Bl,
    float* __restrict__ C, float* __restrict__ C2,
    int M, int N, int K, int Kstride, int NS1, int N2, int nsplit)
{
    constexpr int BK     = 64;
    constexpr int ROWB   = BK * 2;
    constexpr int ABYTES = BM * ROWB;
    constexpr int BBYTES = BN * ROWB;
    constexpr int STAGE  = 2 * ABYTES + 2 * BBYTES;
    constexpr int MT = WM / 16;
    constexpr int NP = WN / 16;
    static_assert((BM / WM) * (BN / WN) == 8, "8 warps");

    extern __shared__ __align__(16) char smem[];

    const int tid  = threadIdx.x;
    const int wid  = tid >> 5;
    const int lane = tid & 31;
    constexpr int WNN = BN / WN;
    const int wm = wid / WNN, wn = wid % WNN;
    const int bm = blockIdx.y * BM, bn = blockIdx.x * BN;
    const int kbase = blockIdx.z * K;
    const uint32_t sbase = smem_u32(smem);
    const int KCH = K >> 6;

    auto load_stage = [&](int s, int c) {
        uint32_t st = sbase + s * STAGE;
        int k0 = kbase + c * BK;
#pragma unroll 2
        for (int idx = tid; idx < BM * 8; idx += 256) {
            int r = idx >> 3, ch = idx & 7;
            size_t g = (size_t)(bm + r) * Kstride + k0 + ch * 8;
            cp16(st + swz(r, ch), Ah + g);
            cp16(st + ABYTES + swz(r, ch), Al + g);
        }
#pragma unroll 2
        for (int idx = tid; idx < BN * 8; idx += 256) {
            int r = idx >> 3, ch = idx & 7;
            size_t g = (size_t)(bn + r) * Kstride + k0 + ch * 8;
            cp16(st + 2 * ABYTES + swz(r, ch), Bh + g);
            cp16(st + 2 * ABYTES + BBYTES + swz(r, ch), Bl + g);
        }
        cp_commit();
    };

    float acc[MT][NP * 2][4];
#pragma unroll
    for (int i = 0; i < MT; i++)
#pragma unroll
        for (int j = 0; j < NP * 2; j++)
#pragma unroll
            for (int q = 0; q < 4; q++) acc[i][j][q] = 0.0f;

    uint32_t ah[2][MT][4], al[2][MT][4], bh[2][NP][4], bl[2][NP][4];

    const int a_row0 = wm * WM + (lane & 15);
    const int a_sel  = lane >> 4;
    const int b_row0 = wn * WN + (lane & 7) + ((lane & 16) >> 1);
    const int b_sel  = (lane >> 3) & 1;

    auto ld_frags = [&](int buf, uint32_t st, int ks) {
#pragma unroll
        for (int mt = 0; mt < MT; ++mt) {
            int row = a_row0 + mt * 16;
            int ch  = ks * 2 + a_sel;
            ldsm_x4(ah[buf][mt], st + swz(row, ch));
            ldsm_x4(al[buf][mt], st + ABYTES + swz(row, ch));
        }
#pragma unroll
        for (int p = 0; p < NP; ++p) {
            int row = b_row0 + p * 16;
            int ch  = ks * 2 + b_sel;
            ldsm_x4(bh[buf][p], st + 2 * ABYTES + swz(row, ch));
            ldsm_x4(bl[buf][p], st + 2 * ABYTES + BBYTES + swz(row, ch));
        }
    };
    auto do_mma = [&](int buf) {
#pragma unroll
        for (int t = 0; t < 3; ++t)
#pragma unroll
            for (int mt = 0; mt < MT; ++mt)
#pragma unroll
                for (int p = 0; p < NP; ++p) {
                    const uint32_t* af = (t == 2) ? al[buf][mt] : ah[buf][mt];
                    const uint32_t* bf = (t == 1) ? bl[buf][p]  : bh[buf][p];
                    mma16816(acc[mt][2 * p],     af, bf);
                    mma16816(acc[mt][2 * p + 1], af, bf + 2);
                }
    };

    load_stage(0, 0);

    for (int c = 0; c < KCH; ++c) {
        cp_wait<0>();
        __syncthreads();
        uint32_t st = sbase + (c & 1) * STAGE;
        ld_frags(0, st, 0);
        if (c + 1 < KCH) load_stage((c + 1) & 1, c + 1);
        else cp_commit();
#pragma unroll
        for (int ks = 0; ks < 4; ++ks) {
            if (ks < 3) ld_frags((ks + 1) & 1, st, ks + 1);
            do_mma(ks & 1);
        }
    }

    // ---- epilogue ----
    float* Cw;
    int Nw = NS1;
    int bnw = bn;
    if (EPI == 0) {
        Cw = C + (size_t)blockIdx.z * (size_t)N2;   // N2 = z-stride (elements)
    } else {
        Cw = C;
        if (bn >= nsplit) { Cw = C2; Nw = N2; bnw = bn - nsplit; }
    }
#pragma unroll
    for (int mt = 0; mt < MT; ++mt) {
        int m0 = bm + wm * WM + mt * 16 + (lane >> 2);
#pragma unroll
        for (int nt = 0; nt < NP * 2; ++nt) {
            int n0 = bnw + wn * WN + nt * 8 + (lane & 3) * 2;
            *(float2*)(Cw + (size_t)m0 * Nw + n0)       = make_float2(acc[mt][nt][0], acc[mt][nt][1]);
            *(float2*)(Cw + (size_t)(m0 + 8) * Nw + n0) = make_float2(acc[mt][nt][2], acc[mt][nt][3]);
        }
    }
}

// ---------------------------------------------------------------------------
// Expansion (closed-form uniform cubic B-spline) + bf16 split.
// Input h = h0 (+ h1 if non-null): fuses the split-K reduction.
// ---------------------------------------------------------------------------
__global__ __launch_bounds__(256) void expand_kernel(
    const float* __restrict__ h0, const float* __restrict__ h1,
    bf16* __restrict__ Ah, bf16* __restrict__ Al) {
    __shared__ __align__(16) bf16 s_hi[256 * 9];
    __shared__ __align__(16) bf16 s_lo[256 * 9];

    int tid  = threadIdx.x;
    int gid  = blockIdx.x;
    int b    = gid >> 1;
    int half = gid & 1;
    int u    = half * 256 + tid;

    size_t hidx = (size_t)b * UNITSN + u;
    float x = h0[hidx];
    if (h1) x += h1[hidx];

    float vals[9];
    vals[0] = x / (1.0f + expf(-x));
#pragma unroll
    for (int k = 1; k < 9; k++) vals[k] = 0.0f;

    int c = -1;
#pragma unroll
    for (int j = 0; j < 12; j++) {
        float gj = (float)(0.4 * (double)(j - 3) - 1.0);
        c += (x >= gj) ? 1 : 0;
    }
    if (c >= 0 && c <= 10) {
        float gc = (float)c * 0.4f - 2.2f;
        float t  = (x - gc) * 2.5f;
        float t2 = t * t, t3 = t2 * t;
        float omt = 1.0f - t;
        float w0 = t3 * (1.0f / 6.0f);
        float w1 = (1.0f + 3.0f * t + 3.0f * t2 - 3.0f * t3) * (1.0f / 6.0f);
        float w2 = (4.0f - 6.0f * t2 + 3.0f * t3) * (1.0f / 6.0f);
        float w3 = omt * omt * omt * (1.0f / 6.0f);
        if (c <= 7)                    vals[1 + c]   = w0;
        if (c - 1 >= 0 && c - 1 <= 7)  vals[c]       = w1;
        if (c - 2 >= 0 && c - 2 <= 7)  vals[c - 1]   = w2;
        if (c - 3 >= 0)                vals[c - 2]   = w3;
    }

#pragma unroll
    for (int f = 0; f < 9; f++) {
        bf16 hv, lv;
        split2(vals[f], hv, lv);
        s_hi[tid * 9 + f] = hv;
        s_lo[tid * 9 + f] = lv;
    }
    __syncthreads();

    size_t elem_base = (size_t)b * KEXPN + half * 2304;
    const uint4* sh = (const uint4*)s_hi;
    const uint4* sl = (const uint4*)s_lo;
    uint4* dh = (uint4*)(Ah + elem_base);
    uint4* dl = (uint4*)(Al + elem_base);
#pragma unroll 2
    for (int j = tid; j < 288; j += 256) { dh[j] = sh[j]; dl[j] = sl[j]; }
}

// ---------------------------------------------------------------------------
// Combine split-K partials -> bf16 hi/lo (theta), vectorized 2 elems/thread
// ---------------------------------------------------------------------------
__global__ void combine_split_kernel(const float* __restrict__ p0,
                                     const float* __restrict__ p1,
                                     bf16* __restrict__ hi, bf16* __restrict__ lo,
                                     int n) {
    int i = (blockIdx.x * blockDim.x + threadIdx.x) * 2;
    if (i < n) {
        float2 a = *(const float2*)(p0 + i);
        float2 b = *(const float2*)(p1 + i);
        float v0 = a.x + b.x, v1 = a.y + b.y;
        bf16 h0, l0, h1, l1;
        split2(v0, h0, l0);
        split2(v1, h1, l1);
        __nv_bfloat162 hv; hv.x = h0; hv.y = h1;
        __nv_bfloat162 lv; lv.x = l0; lv.y = l1;
        *(__nv_bfloat162*)(hi + i) = hv;
        *(__nv_bfloat162*)(lo + i) = lv;
    }
}

// ---------------------------------------------------------------------------
// Weight pack + split into [N][K] bf16 hi/lo, smem transpose tile.
// Tile = 16 outputs x 16 i-units (9 KB smem; FC grid = 1024 CTAs).
// ---------------------------------------------------------------------------
__global__ __launch_bounds__(256) void prepw_kernel(
    const float* __restrict__ coef, const float* __restrict__ sb,
    const float* __restrict__ ssp,
    bf16* __restrict__ Wh, bf16* __restrict__ Wl, int N) {
    extern __shared__ __align__(16) char psm[];
    bf16* s_hi = (bf16*)psm;              // [16][144]
    bf16* s_lo = s_hi + 16 * 144;

    int tid = threadIdx.x;
    int ob0 = blockIdx.x * 16;
    int ib0 = blockIdx.y * 16;

    if (tid < 16 * 16) {
        int i_l = tid >> 4, o_l = tid & 15;
        int i = ib0 + i_l, o = ob0 + o_l;
        size_t idx = (size_t)i * N + o;
        float s   = ssp[idx];
        float sbv = sb[idx];
        const float4* cp = (const float4*)(coef + idx * NCOEFN);
        float4 c0 = cp[0], c1 = cp[1];
        float cv[8] = {c0.x, c0.y, c0.z, c0.w, c1.x, c1.y, c1.z, c1.w};
        bf16* rh = s_hi + o_l * 144 + i_l * 9;
        bf16* rl = s_lo + o_l * 144 + i_l * 9;
        bf16 hv, lv;
        split2(sbv, hv, lv); rh[0] = hv; rl[0] = lv;
#pragma unroll
        for (int k = 0; k < 8; k++) {
            split2(cv[k] * s, hv, lv);
            rh[1 + k] = hv; rl[1 + k] = lv;
        }
    }
    __syncthreads();

    // per output row: 144 bf16 = 288 B = 18 uint4; 16 rows x 18 = 288 uint4
    for (int j = tid; j < 16 * 18; j += 256) {
        int o_l = j / 18, q = j - o_l * 18;
        size_t ebase = (size_t)(ob0 + o_l) * KEXPN + (size_t)ib0 * 9;
        ((uint4*)(Wh + ebase))[q] = ((const uint4*)(s_hi + o_l * 144))[q];
        ((uint4*)(Wl + ebase))[q] = ((const uint4*)(s_lo + o_l * 144))[q];
    }
}

// ---------------------------------------------------------------------------
// Seasonal basis (double trig), combined [640][128] layout, bf16 split
// ---------------------------------------------------------------------------
__global__ void basis_kernel(bf16* Sbh, bf16* Sbl, bf16* Sfh, bf16* Sfl) {
    int idx = blockIdx.x * blockDim.x + threadIdx.x;
    const double step = (639.0 / 640.0) / 639.0;
    const double TWO_PI = 6.283185307179586476925286766559;
    int total_b = BACKN * THN;
    int total_f = FOREN * THN;
    if (idx < total_b) {
        int t = idx / THN, r = idx % THN;
        double lin = (double)t * step;
        int rr = (r < 64) ? r : r - 64;
        double f = (rr == 63) ? 640.0 : (double)rr * (640.0 / 63.0);
        double a = TWO_PI * f * lin;
        bf16 hv, lv;
        split2((float)((r < 64) ? cos(a) : sin(a)), hv, lv);
        Sbh[idx] = hv; Sbl[idx] = lv;
    } else if (idx < total_b + total_f) {
        int j = idx - total_b;
        int t = j / THN, r = j % THN;
        int tt = t + BACKN;
        double lin = (tt == 639) ? (639.0 / 640.0) : (double)tt * step;
        int rr = (r < 64) ? r : r - 64;
        double f = (rr == 63) ? 640.0 : (double)rr * (640.0 / 63.0);
        double a = TWO_PI * f * lin;
        bf16 hv, lv;
        split2((float)((r < 64) ? cos(a) : sin(a)), hv, lv);
        Sfh[j] = hv; Sfl[j] = lv;
    }
}

// ---------------------------------------------------------------------------
// Launch: two half-batch pipelines (stream 0 + s3), no skew;
// prepw + basis on low-priority side stream s2. All regions disjoint.
// ---------------------------------------------------------------------------
extern "C" void kernel_launch(void* const* d_in, const int* in_sizes, int n_in,
                              void* d_out, int out_size) {
    (void)in_sizes; (void)n_in; (void)out_size;
    const float* x       = (const float*)d_in[0];
    const float* coef_fc = (const float*)d_in[1];
    const float* sb_fc   = (const float*)d_in[2];
    const float* ssp_fc  = (const float*)d_in[3];
    const float* coef_th = (const float*)d_in[4];
    const float* sb_th   = (const float*)d_in[5];
    const float* ssp_th  = (const float*)d_in[6];
    float* out = (float*)d_out;

    bf16 *Ah, *Al, *Wh, *Wl, *Thh, *Thl, *Sch, *Scl;
    float *Hbase, *Ptbase;
    cudaGetSymbolAddress((void**)&Ah, g_Ah);
    cudaGetSymbolAddress((void**)&Al, g_Al);
    cudaGetSymbolAddress((void**)&Wh, g_Wh);
    cudaGetSymbolAddress((void**)&Wl, g_Wl);
    cudaGetSymbolAddress((void**)&Hbase, g_H);
    cudaGetSymbolAddress((void**)&Ptbase, g_Pt);
    cudaGetSymbolAddress((void**)&Thh, g_Thh);
    cudaGetSymbolAddress((void**)&Thl, g_Thl);
    cudaGetSymbolAddress((void**)&Sch, g_Sch);
    cudaGetSymbolAddress((void**)&Scl, g_Scl);

    const size_t WSLICE  = (size_t)KEXPN * UNITSN;
    const size_t WOFF_TH = 4 * WSLICE;
    const size_t PZS_FC  = (size_t)NB * UNITSN;    // z-stride for FC partials
    const size_t PZS_TH  = (size_t)NB * THN;       // z-stride for theta partials

    const int SMEM_FC = 2 * (2 * 128 * 128 + 2 * 64 * 128);   // 96 KB
    const int SMEM_TH = 2 * (2 * 64 * 128 + 2 * 32 * 128);    // 48 KB
    const int SMEM_PW = 2 * 16 * 144 * 2;                     // 9 KB
    cudaFuncSetAttribute((const void*)gemm_mma<128, 64, 32, 32, 0>,
                         cudaFuncAttributeMaxDynamicSharedMemorySize, SMEM_FC);
    cudaFuncSetAttribute((const void*)gemm_mma<128, 64, 32, 32, 2>,
                         cudaFuncAttributeMaxDynamicSharedMemorySize, SMEM_FC);
    cudaFuncSetAttribute((const void*)gemm_mma<64, 32, 16, 16, 0>,
                         cudaFuncAttributeMaxDynamicSharedMemorySize, SMEM_TH);
    cudaFuncSetAttribute((const void*)prepw_kernel,
                         cudaFuncAttributeMaxDynamicSharedMemorySize, SMEM_PW);

    cudaStream_t s2 = g_ss.s2;
    cudaStream_t s3 = g_ss.s3;

    // ---- fork side streams ----
    cudaEventRecord(g_ss.evFork, 0);
    cudaStreamWaitEvent(s2, g_ss.evFork, 0);
    cudaStreamWaitEvent(s3, g_ss.evFork, 0);

    // s2: weight packs + basis
    for (int l = 0; l < NLN; l++) {
        prepw_kernel<<<dim3(UNITSN / 16, UNITSN / 16), 256, SMEM_PW, s2>>>(
            coef_fc + (size_t)l * UNITSN * UNITSN * NCOEFN,
            sb_fc  + (size_t)l * UNITSN * UNITSN,
            ssp_fc + (size_t)l * UNITSN * UNITSN,
            Wh + l * WSLICE, Wl + l * WSLICE, UNITSN);
        cudaEventRecord(g_ss.evW[l], s2);
    }
    prepw_kernel<<<dim3(THN / 16, UNITSN / 16), 256, SMEM_PW, s2>>>(
        coef_th, sb_th, ssp_th, Wh + WOFF_TH, Wl + WOFF_TH, THN);
    cudaEventRecord(g_ss.evW[4], s2);
    {
        int total = BACKN * THN + FOREN * THN;
        basis_kernel<<<(total + 255) / 256, 256, 0, s2>>>(
            Sch, Scl, Sch + (size_t)BACKN * THN, Scl + (size_t)BACKN * THN);
        cudaEventRecord(g_ss.evB, s2);
    }

    // ---- two half-batch pipelines ----
    for (int h = 0; h < 2; ++h) {
        cudaStream_t st = (h == 0) ? (cudaStream_t)0 : s3;
        const float* xh  = x + (size_t)h * HB * UNITSN;
        bf16* Ahh = Ah + (size_t)h * HB * KEXPN;
        bf16* Alh = Al + (size_t)h * HB * KEXPN;
        float* P0h  = Hbase  + (size_t)h * HB * UNITSN;   // FC partial z=0
        float* P1h  = P0h + PZS_FC;                       // FC partial z=1
        float* Pt0h = Ptbase + (size_t)h * HB * THN;      // theta partial z=0
        float* Pt1h = Pt0h + PZS_TH;                      // theta partial z=1
        bf16* Thhh = Thh + (size_t)h * HB * THN;
        bf16* Thlh = Thl + (size_t)h * HB * THN;

        // FC chain
        const float* hin0 = xh;
        const float* hin1 = nullptr;
        for (int l = 0; l < NLN; l++) {
            expand_kernel<<<HB * 2, 256, 0, st>>>(hin0, hin1, Ahh, Alh);
            cudaStreamWaitEvent(st, g_ss.evW[l], 0);
            gemm_mma<128, 64, 32, 32, 0>
                <<<dim3(UNITSN / 64, HB / 128, 2), 256, SMEM_FC, st>>>(
                Ahh, Alh, Wh + l * WSLICE, Wl + l * WSLICE, P0h, nullptr,
                HB, UNITSN, KEXPN / 2, KEXPN, UNITSN, (int)PZS_FC, UNITSN);
            hin0 = P0h; hin1 = P1h;
        }

        // theta layer (512 -> 128), split-K=2 into dedicated g_Pt
        expand_kernel<<<HB * 2, 256, 0, st>>>(hin0, hin1, Ahh, Alh);
        cudaStreamWaitEvent(st, g_ss.evW[4], 0);
        gemm_mma<64, 32, 16, 16, 0>
            <<<dim3(THN / 32, HB / 64, 2), 256, SMEM_TH, st>>>(
            Ahh, Alh, Wh + WOFF_TH, Wl + WOFF_TH, Pt0h, nullptr,
            HB, THN, KEXPN / 2, KEXPN, THN, (int)PZS_TH, THN);
        combine_split_kernel<<<(HB * THN / 2 + 255) / 256, 256, 0, st>>>(
            Pt0h, Pt1h, Thhh, Thlh, HB * THN);

        // backcast + forecast merged: theta @ [Sb|Sf] (N=640, K=128)
        cudaStreamWaitEvent(st, g_ss.evB, 0);
        gemm_mma<128, 64, 32, 32, 2>
            <<<dim3((BACKN + FOREN) / 64, HB / 128, 1), 256, SMEM_FC, st>>>(
            Thhh, Thlh, Sch, Scl,
            out + (size_t)h * HB * BACKN,
            out + (size_t)NB * BACKN + (size_t)h * HB * FOREN,
            HB, BACKN + FOREN, THN, THN, BACKN, FOREN, BACKN);
    }

    // ---- join s3 back into the capture origin stream ----
    cudaEventRecord(g_ss.evJoin, s3);
    cudaStreamWaitEvent((cudaStream_t)0, g_ss.evJoin, 0);
}